// round 12
// baseline (speedup 1.0000x reference)
#include <cuda_runtime.h>
#include <cuda_bf16.h>
#include <math.h>
#include <stdint.h>

// ---------------- problem constants ----------------
#define BSZ   64
#define LSEQ  2688
#define CDIM  256
#define WWIN  42
#define SSH   21
#define NHEAD 8
#define HDIM  32
#define NWIN  64
#define MLPH  1024
#define NTOK  (BSZ*LSEQ)    // 172032
#define NBWIN (BSZ*NWIN)    // 4096

typedef __nv_bfloat16  bf16;
typedef __nv_bfloat162 bf162;

// ---------------- scratch ----------------
__device__ bf16  gb_h0 [(size_t)NTOK*CDIM];
__device__ bf16  gb_qkv[(size_t)NTOK*3*CDIM];
__device__ bf16  gb_att[(size_t)NTOK*CDIM];
__device__ bf16  gb_prj[(size_t)NTOK*CDIM];
__device__ float g_x1  [(size_t)NTOK*CDIM];
__device__ bf16  gb_m  [(size_t)NTOK*CDIM];
__device__ bf16  gb_f1 [(size_t)NTOK*MLPH];
#define WOFF_QKV 0
#define WOFF_P   196608
#define WOFF_F1  262144
#define WOFF_F2  524288
__device__ bf16  gb_w  [786432];

// ------- merged fp32 -> bf16 weight convert (all 4 weights, 1 launch) -----
__global__ __launch_bounds__(256) void cvt_all_kernel(
    const float4* __restrict__ s0, const float4* __restrict__ s1,
    const float4* __restrict__ s2, const float4* __restrict__ s3,
    bf16* __restrict__ wb)
{
    int i = blockIdx.x*256 + threadIdx.x;   // 0 .. 196607
    const float4* src;
    bf162* dst;
    if (i < 49152)        { src = s0 + i;            dst = (bf162*)(wb + WOFF_QKV) + 2*i; }
    else if (i < 65536)   { int j = i - 49152;  src = s1 + j; dst = (bf162*)(wb + WOFF_P)  + 2*j; }
    else if (i < 131072)  { int j = i - 65536;  src = s2 + j; dst = (bf162*)(wb + WOFF_F1) + 2*j; }
    else                  { int j = i - 131072; src = s3 + j; dst = (bf162*)(wb + WOFF_F2) + 2*j; }
    float4 v = *src;
    dst[0] = bf162{__float2bfloat16(v.x), __float2bfloat16(v.y)};
    dst[1] = bf162{__float2bfloat16(v.z), __float2bfloat16(v.w)};
}

// ---------------- LayerNorm (+cyclic shift) -> bf16, 2 tokens/warp ------
__global__ __launch_bounds__(256) void ln_roll_kernel(
    const float* __restrict__ x, const float* __restrict__ g,
    const float* __restrict__ b, bf16* __restrict__ out)
{
    const int warp = threadIdx.x >> 5, lane = threadIdx.x & 31;
    const int tok0 = blockIdx.x * 16 + warp * 2;

    // token A = tok0, token B = tok0+1
    int biA = tok0 / LSEQ, lA = tok0 - biA*LSEQ;
    int tokB = tok0 + 1;
    int biB = tokB / LSEQ, lB = tokB - biB*LSEQ;
    int srcA = biA * LSEQ + (lA + SSH) % LSEQ;
    int srcB = biB * LSEQ + (lB + SSH) % LSEQ;

    const float4* xrA = (const float4*)(x + (size_t)srcA * CDIM);
    const float4* xrB = (const float4*)(x + (size_t)srcB * CDIM);
    float4 a0 = xrA[lane], a1 = xrA[lane + 32];
    float4 c0 = xrB[lane], c1 = xrB[lane + 32];

    float sA  = a0.x+a0.y+a0.z+a0.w + a1.x+a1.y+a1.z+a1.w;
    float ssA = a0.x*a0.x+a0.y*a0.y+a0.z*a0.z+a0.w*a0.w
              + a1.x*a1.x+a1.y*a1.y+a1.z*a1.z+a1.w*a1.w;
    float sB  = c0.x+c0.y+c0.z+c0.w + c1.x+c1.y+c1.z+c1.w;
    float ssB = c0.x*c0.x+c0.y*c0.y+c0.z*c0.z+c0.w*c0.w
              + c1.x*c1.x+c1.y*c1.y+c1.z*c1.z+c1.w*c1.w;
    #pragma unroll
    for (int o = 16; o; o >>= 1) {
        sA  += __shfl_xor_sync(0xffffffffu, sA,  o);
        ssA += __shfl_xor_sync(0xffffffffu, ssA, o);
        sB  += __shfl_xor_sync(0xffffffffu, sB,  o);
        ssB += __shfl_xor_sync(0xffffffffu, ssB, o);
    }
    float mA = sA * (1.0f/CDIM), mB = sB * (1.0f/CDIM);
    float iA = rsqrtf(ssA*(1.0f/CDIM) - mA*mA + 1e-5f);
    float iB = rsqrtf(ssB*(1.0f/CDIM) - mB*mB + 1e-5f);

    float4 g0 = ((const float4*)g)[lane], g1 = ((const float4*)g)[lane+32];
    float4 b0 = ((const float4*)b)[lane], b1 = ((const float4*)b)[lane+32];

    bf162* oA = (bf162*)(out + (size_t)tok0 * CDIM);
    bf162* oB = (bf162*)(out + (size_t)tokB * CDIM);
    oA[2*lane]      = bf162{__float2bfloat16((a0.x-mA)*iA*g0.x+b0.x),
                            __float2bfloat16((a0.y-mA)*iA*g0.y+b0.y)};
    oA[2*lane+1]    = bf162{__float2bfloat16((a0.z-mA)*iA*g0.z+b0.z),
                            __float2bfloat16((a0.w-mA)*iA*g0.w+b0.w)};
    oA[64+2*lane]   = bf162{__float2bfloat16((a1.x-mA)*iA*g1.x+b1.x),
                            __float2bfloat16((a1.y-mA)*iA*g1.y+b1.y)};
    oA[64+2*lane+1] = bf162{__float2bfloat16((a1.z-mA)*iA*g1.z+b1.z),
                            __float2bfloat16((a1.w-mA)*iA*g1.w+b1.w)};
    oB[2*lane]      = bf162{__float2bfloat16((c0.x-mB)*iB*g0.x+b0.x),
                            __float2bfloat16((c0.y-mB)*iB*g0.y+b0.y)};
    oB[2*lane+1]    = bf162{__float2bfloat16((c0.z-mB)*iB*g0.z+b0.z),
                            __float2bfloat16((c0.w-mB)*iB*g0.w+b0.w)};
    oB[64+2*lane]   = bf162{__float2bfloat16((c1.x-mB)*iB*g1.x+b1.x),
                            __float2bfloat16((c1.y-mB)*iB*g1.y+b1.y)};
    oB[64+2*lane+1] = bf162{__float2bfloat16((c1.z-mB)*iB*g1.z+b1.z),
                            __float2bfloat16((c1.w-mB)*iB*g1.w+b1.w)};
}

// --- residual (reverse shift, bf16 proj) + LN2, 2 tokens/warp ---------
__global__ __launch_bounds__(256) void resid_ln2_kernel(
    const float* __restrict__ x,  const bf16* __restrict__ po,
    const float* __restrict__ g,  const float* __restrict__ b,
    float* __restrict__ x1, bf16* __restrict__ m)
{
    const int warp = threadIdx.x >> 5, lane = threadIdx.x & 31;
    const int tok0 = blockIdx.x * 16 + warp * 2;
    const int tokB = tok0 + 1;

    int biA = tok0 / LSEQ, lA = tok0 - biA*LSEQ;
    int biB = tokB / LSEQ, lB = tokB - biB*LSEQ;
    int srcA = biA * LSEQ + (lA - SSH + LSEQ) % LSEQ;
    int srcB = biB * LSEQ + (lB - SSH + LSEQ) % LSEQ;

    const float4* xrA = (const float4*)(x + (size_t)tok0 * CDIM);
    const float4* xrB = (const float4*)(x + (size_t)tokB * CDIM);
    const bf162* prA = (const bf162*)(po + (size_t)srcA * CDIM);
    const bf162* prB = (const bf162*)(po + (size_t)srcB * CDIM);

    float4 a0 = xrA[lane], a1 = xrA[lane+32];
    float4 c0 = xrB[lane], c1 = xrB[lane+32];
    float2 pA00 = __bfloat1622float2(prA[2*lane]);
    float2 pA01 = __bfloat1622float2(prA[2*lane+1]);
    float2 pA10 = __bfloat1622float2(prA[64+2*lane]);
    float2 pA11 = __bfloat1622float2(prA[64+2*lane+1]);
    float2 pB00 = __bfloat1622float2(prB[2*lane]);
    float2 pB01 = __bfloat1622float2(prB[2*lane+1]);
    float2 pB10 = __bfloat1622float2(prB[64+2*lane]);
    float2 pB11 = __bfloat1622float2(prB[64+2*lane+1]);

    float4 vA0, vA1, vB0, vB1;
    vA0.x=a0.x+pA00.x; vA0.y=a0.y+pA00.y; vA0.z=a0.z+pA01.x; vA0.w=a0.w+pA01.y;
    vA1.x=a1.x+pA10.x; vA1.y=a1.y+pA10.y; vA1.z=a1.z+pA11.x; vA1.w=a1.w+pA11.y;
    vB0.x=c0.x+pB00.x; vB0.y=c0.y+pB00.y; vB0.z=c0.z+pB01.x; vB0.w=c0.w+pB01.y;
    vB1.x=c1.x+pB10.x; vB1.y=c1.y+pB10.y; vB1.z=c1.z+pB11.x; vB1.w=c1.w+pB11.y;

    float4* x1A = (float4*)(x1 + (size_t)tok0 * CDIM);
    float4* x1B = (float4*)(x1 + (size_t)tokB * CDIM);
    x1A[lane] = vA0; x1A[lane+32] = vA1;
    x1B[lane] = vB0; x1B[lane+32] = vB1;

    float sA  = vA0.x+vA0.y+vA0.z+vA0.w + vA1.x+vA1.y+vA1.z+vA1.w;
    float ssA = vA0.x*vA0.x+vA0.y*vA0.y+vA0.z*vA0.z+vA0.w*vA0.w
              + vA1.x*vA1.x+vA1.y*vA1.y+vA1.z*vA1.z+vA1.w*vA1.w;
    float sB  = vB0.x+vB0.y+vB0.z+vB0.w + vB1.x+vB1.y+vB1.z+vB1.w;
    float ssB = vB0.x*vB0.x+vB0.y*vB0.y+vB0.z*vB0.z+vB0.w*vB0.w
              + vB1.x*vB1.x+vB1.y*vB1.y+vB1.z*vB1.z+vB1.w*vB1.w;
    #pragma unroll
    for (int o = 16; o; o >>= 1) {
        sA  += __shfl_xor_sync(0xffffffffu, sA,  o);
        ssA += __shfl_xor_sync(0xffffffffu, ssA, o);
        sB  += __shfl_xor_sync(0xffffffffu, sB,  o);
        ssB += __shfl_xor_sync(0xffffffffu, ssB, o);
    }
    float mA = sA * (1.0f/CDIM), mB = sB * (1.0f/CDIM);
    float iA = rsqrtf(ssA*(1.0f/CDIM) - mA*mA + 1e-5f);
    float iB = rsqrtf(ssB*(1.0f/CDIM) - mB*mB + 1e-5f);

    float4 g0 = ((const float4*)g)[lane], g1 = ((const float4*)g)[lane+32];
    float4 b0 = ((const float4*)b)[lane], b1 = ((const float4*)b)[lane+32];

    bf162* mA_ = (bf162*)(m + (size_t)tok0 * CDIM);
    bf162* mB_ = (bf162*)(m + (size_t)tokB * CDIM);
    mA_[2*lane]      = bf162{__float2bfloat16((vA0.x-mA)*iA*g0.x+b0.x),
                             __float2bfloat16((vA0.y-mA)*iA*g0.y+b0.y)};
    mA_[2*lane+1]    = bf162{__float2bfloat16((vA0.z-mA)*iA*g0.z+b0.z),
                             __float2bfloat16((vA0.w-mA)*iA*g0.w+b0.w)};
    mA_[64+2*lane]   = bf162{__float2bfloat16((vA1.x-mA)*iA*g1.x+b1.x),
                             __float2bfloat16((vA1.y-mA)*iA*g1.y+b1.y)};
    mA_[64+2*lane+1] = bf162{__float2bfloat16((vA1.z-mA)*iA*g1.z+b1.z),
                             __float2bfloat16((vA1.w-mA)*iA*g1.w+b1.w)};
    mB_[2*lane]      = bf162{__float2bfloat16((vB0.x-mB)*iB*g0.x+b0.x),
                             __float2bfloat16((vB0.y-mB)*iB*g0.y+b0.y)};
    mB_[2*lane+1]    = bf162{__float2bfloat16((vB0.z-mB)*iB*g0.z+b0.z),
                             __float2bfloat16((vB0.w-mB)*iB*g0.w+b0.w)};
    mB_[64+2*lane]   = bf162{__float2bfloat16((vB1.x-mB)*iB*g1.x+b1.x),
                             __float2bfloat16((vB1.y-mB)*iB*g1.y+b1.y)};
    mB_[64+2*lane+1] = bf162{__float2bfloat16((vB1.z-mB)*iB*g1.z+b1.z),
                             __float2bfloat16((vB1.w-mB)*iB*g1.w+b1.w)};
}

// ---------------- mma helpers ---------------------
__device__ __forceinline__ float gelu_exact(float v) {
    return 0.5f * v * (1.0f + erff(v * 0.70710678118654752f));
}
__device__ __forceinline__ void cpasync16(uint32_t saddr, const void* g) {
    asm volatile("cp.async.cg.shared.global [%0], [%1], 16;\n" :: "r"(saddr), "l"(g));
}
__device__ __forceinline__ void ldsm_x4(uint32_t* r, uint32_t a) {
    asm volatile("ldmatrix.sync.aligned.m8n8.x4.shared.b16 {%0,%1,%2,%3}, [%4];"
        : "=r"(r[0]), "=r"(r[1]), "=r"(r[2]), "=r"(r[3]) : "r"(a));
}
__device__ __forceinline__ void ldsm_x4t(uint32_t* r, uint32_t a) {
    asm volatile("ldmatrix.sync.aligned.m8n8.x4.trans.shared.b16 {%0,%1,%2,%3}, [%4];"
        : "=r"(r[0]), "=r"(r[1]), "=r"(r[2]), "=r"(r[3]) : "r"(a));
}
__device__ __forceinline__ void mma_bf16(
    float& c0, float& c1, float& c2, float& c3,
    uint32_t a0, uint32_t a1, uint32_t a2, uint32_t a3,
    uint32_t b0, uint32_t b1)
{
    asm volatile(
        "mma.sync.aligned.m16n8k16.row.col.f32.bf16.bf16.f32 "
        "{%0,%1,%2,%3}, {%4,%5,%6,%7}, {%8,%9}, {%0,%1,%2,%3};\n"
        : "+f"(c0), "+f"(c1), "+f"(c2), "+f"(c3)
        : "r"(a0), "r"(a1), "r"(a2), "r"(a3), "r"(b0), "r"(b1));
}
__device__ __forceinline__ uint32_t packbf(float x, float y) {
    bf162 p = bf162{__float2bfloat16(x), __float2bfloat16(y)};
    return *(uint32_t*)&p;
}

// ------- bf16 GEMM: 128x128 block, warp 64x32, 4-stage cp.async (R8) ----
#define BKK   32
#define LDAg  40
#define LDBg  136
#define ASZ   (128*LDAg*2)
#define BSZB  (BKK*LDBg*2)
#define STG   (ASZ + BSZB)
#define NSTG  4
#define GM_SMEM (NSTG*STG)

template<int EPI, int OUTBF>
__global__ __launch_bounds__(256) void bgemm_kernel(
    const bf16* __restrict__ A, const bf16* __restrict__ Bw,
    const float* __restrict__ bias, const float* __restrict__ res,
    void* __restrict__ Cv, int M, int N, int K)
{
    extern __shared__ __align__(16) char gsm[];
    const uint32_t smBase = (uint32_t)__cvta_generic_to_shared(gsm);

    const int tid  = threadIdx.x;
    const int warp = tid >> 5, lane = tid & 31;
    const int wm  = (warp >> 2) * 64;
    const int wn  = (warp & 3) * 32;
    const int grp = lane & 3;
    const int qid = lane >> 2;

    const int arow = tid >> 1, acol = (tid & 1) * 16;
    const int brow = tid >> 3, bcol = (tid & 7) * 16;
    const bf16* Ag = A  + (size_t)(blockIdx.y*128 + arow) * K + acol;
    const bf16* Bg = Bw + (size_t)brow * N + blockIdx.x*128 + bcol;

    const uint32_t asOff = (uint32_t)(arow*LDAg + acol) * 2;
    const uint32_t bsOff = (uint32_t)(brow*LDBg + bcol) * 2 + ASZ;

    float acc[4][4][4];
    #pragma unroll
    for (int i = 0; i < 4; i++)
        #pragma unroll
        for (int j = 0; j < 4; j++)
            #pragma unroll
            for (int t = 0; t < 4; t++) acc[i][j][t] = 0.0f;

    const int NIT = K / BKK;

    #pragma unroll
    for (int s = 0; s < NSTG-1; s++) {
        const int k0 = s * BKK;
        if (s < NIT) {
            uint32_t st = smBase + s*STG;
            cpasync16(st + asOff,      Ag + k0);
            cpasync16(st + asOff + 16, Ag + k0 + 8);
            cpasync16(st + bsOff,      Bg + (size_t)k0*N);
            cpasync16(st + bsOff + 16, Bg + (size_t)k0*N + 8);
        }
        asm volatile("cp.async.commit_group;\n");
    }

    int buf = 0;
    for (int it = 0; it < NIT; it++) {
        asm volatile("cp.async.wait_group 2;\n");
        __syncthreads();

        if (it + NSTG - 1 < NIT) {
            const int k0 = (it + NSTG - 1) * BKK;
            int nb = (buf + NSTG - 1) & (NSTG - 1);
            uint32_t st = smBase + nb*STG;
            cpasync16(st + asOff,      Ag + k0);
            cpasync16(st + asOff + 16, Ag + k0 + 8);
            cpasync16(st + bsOff,      Bg + (size_t)k0*N);
            cpasync16(st + bsOff + 16, Bg + (size_t)k0*N + 8);
        }
        asm volatile("cp.async.commit_group;\n");

        uint32_t asB = smBase + buf*STG;
        uint32_t bsB = asB + ASZ;

        #pragma unroll
        for (int ks = 0; ks < 2; ks++) {
            const int kb = ks * 16;
            uint32_t af[4][4];
            #pragma unroll
            for (int mi = 0; mi < 4; mi++) {
                int row = wm + mi*16 + (lane & 15);
                ldsm_x4(af[mi], asB + ((uint32_t)(row*LDAg + kb + (lane >> 4)*8)) * 2);
            }
            uint32_t bfr[2][4];
            #pragma unroll
            for (int gj = 0; gj < 2; gj++) {
                int krow = kb + (lane & 7) + ((lane >> 3) & 1) * 8;
                int col  = wn + gj*16 + (lane >> 4) * 8;
                ldsm_x4t(bfr[gj], bsB + ((uint32_t)(krow*LDBg + col)) * 2);
            }
            #pragma unroll
            for (int mi = 0; mi < 4; mi++)
                #pragma unroll
                for (int nj = 0; nj < 4; nj++)
                    mma_bf16(acc[mi][nj][0], acc[mi][nj][1],
                             acc[mi][nj][2], acc[mi][nj][3],
                             af[mi][0], af[mi][1], af[mi][2], af[mi][3],
                             bfr[nj >> 1][(nj & 1)*2], bfr[nj >> 1][(nj & 1)*2 + 1]);
        }
        buf = (buf + 1) & (NSTG - 1);
    }

    const int row0 = blockIdx.y*128 + wm;
    const int col0 = blockIdx.x*128 + wn;
    #pragma unroll
    for (int mi = 0; mi < 4; mi++) {
        #pragma unroll
        for (int nj = 0; nj < 4; nj++) {
            int c = col0 + nj*8 + grp*2;
            float bv0 = bias[c], bv1 = bias[c+1];
            #pragma unroll
            for (int half = 0; half < 2; half++) {
                int r = row0 + mi*16 + qid + half*8;
                float v0 = acc[mi][nj][half*2+0] + bv0;
                float v1 = acc[mi][nj][half*2+1] + bv1;
                size_t off = (size_t)r * N + c;
                if (EPI == 1) { v0 = gelu_exact(v0); v1 = gelu_exact(v1); }
                if (EPI == 2) { v0 += res[off]; v1 += res[off+1]; }
                if (OUTBF) {
                    bf162 o = {__float2bfloat16(v0), __float2bfloat16(v1)};
                    *(bf162*)((bf16*)Cv + off) = o;
                } else {
                    float2 o = {v0, v1};
                    *(float2*)((float*)Cv + off) = o;
                }
            }
        }
    }
}

// ============ tensor-core windowed attention (staging optimized) =======
#define APAD 40
#define ATT_SMEM (3*8*48*APAD*2 + 8*84*4)

__global__ __launch_bounds__(256) void attn_mma_kernel(
    const bf16* __restrict__ qkv, const float* __restrict__ bias_table,
    bf16* __restrict__ out)
{
    extern __shared__ __align__(16) char smraw[];
    bf16* sq = (bf16*)smraw;
    bf16* sk = sq + 8*48*APAD;
    bf16* sv = sk + 8*48*APAD;
    float* sb = (float*)(sv + 8*48*APAD);

    const int w = blockIdx.x;
    const int tid = threadIdx.x, warp = tid >> 5, lane = tid & 31;

    // ---- staging: incremental (t,r) avoids per-iter div/mod ----
    const uint4* src = (const uint4*)(qkv + (size_t)w * WWIN * 768);
    {
        int c = tid;
        int t = tid / 96, r = tid - t*96;   // one div at entry
        while (c < WWIN*96) {
            int kind = r >> 5;
            int hh   = (r & 31) >> 2;
            int d8   = r & 3;
            uint4 val = src[c];
            bf16* dst = (kind == 0 ? sq : (kind == 1 ? sk : sv))
                      + (hh*48 + t)*APAD + d8*8;
            *(uint4*)dst = val;
            c += 256; t += 2; r += 64;
            if (r >= 96) { r -= 96; t += 1; }
        }
    }
    for (int c = tid; c < 8*6*4; c += 256) {
        int hh = c / 24, r6 = (c / 4) % 6, d8 = c & 3;
        uint4 z = {0,0,0,0};
        *(uint4*)(sq + (hh*48 + 42 + r6)*APAD + d8*8) = z;
        *(uint4*)(sk + (hh*48 + 42 + r6)*APAD + d8*8) = z;
        *(uint4*)(sv + (hh*48 + 42 + r6)*APAD + d8*8) = z;
    }
    for (int c = tid; c < 83*8; c += 256) {
        int d = c >> 3, hh = c & 7;
        sb[hh*84 + d] = bias_table[d*8 + hh];
    }
    __syncthreads();

    const int h = warp;
    const uint32_t qb = (uint32_t)__cvta_generic_to_shared(sq + h*48*APAD);
    const uint32_t kb = (uint32_t)__cvta_generic_to_shared(sk + h*48*APAD);
    const uint32_t vb = (uint32_t)__cvta_generic_to_shared(sv + h*48*APAD);
    const float* bh = sb + h*84;
    const bool lastw = ((w & (NWIN-1)) == NWIN-1);

    float s[3][6][4];
    #pragma unroll
    for (int i = 0; i < 3; i++)
        #pragma unroll
        for (int j = 0; j < 6; j++)
            #pragma unroll
            for (int t = 0; t < 4; t++) s[i][j][t] = 0.0f;

    #pragma unroll
    for (int kt = 0; kt < 2; kt++) {
        uint32_t af[3][4], bfr[3][4];
        #pragma unroll
        for (int mi = 0; mi < 3; mi++) {
            int row = mi*16 + (lane & 15);
            ldsm_x4(af[mi], qb + ((uint32_t)(row*APAD + kt*16 + (lane >> 4)*8))*2);
        }
        #pragma unroll
        for (int np = 0; np < 3; np++) {
            int row = np*16 + (lane >> 4)*8 + (lane & 7);
            int col = kt*16 + ((lane >> 3) & 1)*8;
            ldsm_x4(bfr[np], kb + ((uint32_t)(row*APAD + col))*2);
        }
        #pragma unroll
        for (int mi = 0; mi < 3; mi++)
            #pragma unroll
            for (int nj = 0; nj < 6; nj++)
                mma_bf16(s[mi][nj][0], s[mi][nj][1], s[mi][nj][2], s[mi][nj][3],
                         af[mi][0], af[mi][1], af[mi][2], af[mi][3],
                         bfr[nj >> 1][(nj & 1)*2], bfr[nj >> 1][(nj & 1)*2 + 1]);
    }

    const int rA0 = lane >> 2;
    const int colb = (lane & 3)*2;
    #pragma unroll
    for (int mi = 0; mi < 3; mi++) {
        int rA = mi*16 + rA0, rB = rA + 8;
        #pragma unroll
        for (int nj = 0; nj < 6; nj++) {
            int c0 = nj*8 + colb, c1 = c0 + 1;
            int dA0 = min(max(c0 - rA + 41, 0), 82);
            int dA1 = min(max(c1 - rA + 41, 0), 82);
            int dB0 = min(max(c0 - rB + 41, 0), 82);
            int dB1 = min(max(c1 - rB + 41, 0), 82);
            float v0 = s[mi][nj][0]*0.17677669529663688f + bh[dA0];
            float v1 = s[mi][nj][1]*0.17677669529663688f + bh[dA1];
            if (lastw && ((rA < SSH) != (c0 < SSH))) v0 -= 100.0f;
            if (lastw && ((rA < SSH) != (c1 < SSH))) v1 -= 100.0f;
            if (c0 >= WWIN) v0 = -1e30f;
            if (c1 >= WWIN) v1 = -1e30f;
            float v2 = s[mi][nj][2]*0.17677669529663688f + bh[dB0];
            float v3 = s[mi][nj][3]*0.17677669529663688f + bh[dB1];
            if (lastw && ((rB < SSH) != (c0 < SSH))) v2 -= 100.0f;
            if (lastw && ((rB < SSH) != (c1 < SSH))) v3 -= 100.0f;
            if (c0 >= WWIN) v2 = -1e30f;
            if (c1 >= WWIN) v3 = -1e30f;
            s[mi][nj][0] = v0; s[mi][nj][1] = v1;
            s[mi][nj][2] = v2; s[mi][nj][3] = v3;
        }
        float mxA = -1e30f, mxB = -1e30f;
        #pragma unroll
        for (int nj = 0; nj < 6; nj++) {
            mxA = fmaxf(mxA, fmaxf(s[mi][nj][0], s[mi][nj][1]));
            mxB = fmaxf(mxB, fmaxf(s[mi][nj][2], s[mi][nj][3]));
        }
        mxA = fmaxf(mxA, __shfl_xor_sync(0xffffffffu, mxA, 1));
        mxA = fmaxf(mxA, __shfl_xor_sync(0xffffffffu, mxA, 2));
        mxB = fmaxf(mxB, __shfl_xor_sync(0xffffffffu, mxB, 1));
        mxB = fmaxf(mxB, __shfl_xor_sync(0xffffffffu, mxB, 2));
        float smA = 0.0f, smB = 0.0f;
        #pragma unroll
        for (int nj = 0; nj < 6; nj++) {
            float e0 = __expf(s[mi][nj][0] - mxA);
            float e1 = __expf(s[mi][nj][1] - mxA);
            float e2 = __expf(s[mi][nj][2] - mxB);
            float e3 = __expf(s[mi][nj][3] - mxB);
            s[mi][nj][0] = e0; s[mi][nj][1] = e1;
            s[mi][nj][2] = e2; s[mi][nj][3] = e3;
            smA += e0 + e1; smB += e2 + e3;
        }
        smA += __shfl_xor_sync(0xffffffffu, smA, 1);
        smA += __shfl_xor_sync(0xffffffffu, smA, 2);
        smB += __shfl_xor_sync(0xffffffffu, smB, 1);
        smB += __shfl_xor_sync(0xffffffffu, smB, 2);
        float rAi = 1.0f / smA, rBi = 1.0f / smB;
        #pragma unroll
        for (int nj = 0; nj < 6; nj++) {
            s[mi][nj][0] *= rAi; s[mi][nj][1] *= rAi;
            s[mi][nj][2] *= rBi; s[mi][nj][3] *= rBi;
        }
    }

    float o[3][4][4];
    #pragma unroll
    for (int i = 0; i < 3; i++)
        #pragma unroll
        for (int j = 0; j < 4; j++)
            #pragma unroll
            for (int t = 0; t < 4; t++) o[i][j][t] = 0.0f;

    #pragma unroll
    for (int kt = 0; kt < 3; kt++) {
        uint32_t bfr[2][4];
        #pragma unroll
        for (int gj = 0; gj < 2; gj++) {
            int krow = kt*16 + (lane & 7) + ((lane >> 3) & 1)*8;
            int col  = gj*16 + (lane >> 4)*8;
            ldsm_x4t(bfr[gj], vb + ((uint32_t)(krow*APAD + col))*2);
        }
        #pragma unroll
        for (int mi = 0; mi < 3; mi++) {
            uint32_t a0 = packbf(s[mi][2*kt][0],   s[mi][2*kt][1]);
            uint32_t a1 = packbf(s[mi][2*kt][2],   s[mi][2*kt][3]);
            uint32_t a2 = packbf(s[mi][2*kt+1][0], s[mi][2*kt+1][1]);
            uint32_t a3 = packbf(s[mi][2*kt+1][2], s[mi][2*kt+1][3]);
            #pragma unroll
            for (int nj = 0; nj < 4; nj++)
                mma_bf16(o[mi][nj][0], o[mi][nj][1], o[mi][nj][2], o[mi][nj][3],
                         a0, a1, a2, a3,
                         bfr[nj >> 1][(nj & 1)*2], bfr[nj >> 1][(nj & 1)*2 + 1]);
        }
    }

    #pragma unroll
    for (int mi = 0; mi < 3; mi++) {
        int rA = mi*16 + rA0, rB = rA + 8;
        #pragma unroll
        for (int nj = 0; nj < 4; nj++) {
            int c = nj*8 + colb;
            if (rA < WWIN) {
                bf162 p = bf162{__float2bfloat16(o[mi][nj][0]), __float2bfloat16(o[mi][nj][1])};
                *(bf162*)(out + ((size_t)w*WWIN + rA)*CDIM + h*HDIM + c) = p;
            }
            if (rB < WWIN) {
                bf162 p = bf162{__float2bfloat16(o[mi][nj][2]), __float2bfloat16(o[mi][nj][3])};
                *(bf162*)(out + ((size_t)w*WWIN + rB)*CDIM + h*HDIM + c) = p;
            }
        }
    }
}

// ---------------- host-side launch --------------------------
extern "C" void kernel_launch(void* const* d_in, const int* in_sizes, int n_in,
                              void* d_out, int out_size)
{
    const float* x     = (const float*)d_in[0];
    const float* n1g   = (const float*)d_in[1];
    const float* n1b   = (const float*)d_in[2];
    const float* qkv_w = (const float*)d_in[3];
    const float* qkv_b = (const float*)d_in[4];
    const float* bt    = (const float*)d_in[5];
    const float* pw    = (const float*)d_in[6];
    const float* pb    = (const float*)d_in[7];
    const float* n2g   = (const float*)d_in[8];
    const float* n2b   = (const float*)d_in[9];
    const float* f1w   = (const float*)d_in[10];
    const float* f1b   = (const float*)d_in[11];
    const float* f2w   = (const float*)d_in[12];
    const float* f2b   = (const float*)d_in[13];
    float* out = (float*)d_out;

    bf16 *h0b, *qkvb, *attb, *prjb, *mb, *f1buf, *wb;
    float *x1;
    cudaGetSymbolAddress((void**)&h0b,  gb_h0);
    cudaGetSymbolAddress((void**)&qkvb, gb_qkv);
    cudaGetSymbolAddress((void**)&attb, gb_att);
    cudaGetSymbolAddress((void**)&prjb, gb_prj);
    cudaGetSymbolAddress((void**)&x1,   g_x1);
    cudaGetSymbolAddress((void**)&mb,   gb_m);
    cudaGetSymbolAddress((void**)&f1buf,gb_f1);
    cudaGetSymbolAddress((void**)&wb,   gb_w);

    cudaFuncSetAttribute(attn_mma_kernel,
                         cudaFuncAttributeMaxDynamicSharedMemorySize, ATT_SMEM);
    cudaFuncSetAttribute(bgemm_kernel<0,1>,
                         cudaFuncAttributeMaxDynamicSharedMemorySize, GM_SMEM);
    cudaFuncSetAttribute(bgemm_kernel<1,1>,
                         cudaFuncAttributeMaxDynamicSharedMemorySize, GM_SMEM);
    cudaFuncSetAttribute(bgemm_kernel<2,0>,
                         cudaFuncAttributeMaxDynamicSharedMemorySize, GM_SMEM);

    cvt_all_kernel<<<768, 256>>>((const float4*)qkv_w, (const float4*)pw,
                                 (const float4*)f1w,   (const float4*)f2w, wb);

    const int MBLK = NTOK / 128;   // 1344

    ln_roll_kernel<<<NTOK/16, 256>>>(x, n1g, n1b, h0b);
    bgemm_kernel<0,1><<<dim3(6, MBLK), 256, GM_SMEM>>>(h0b, wb + WOFF_QKV, qkv_b, nullptr, qkvb, NTOK, 768, 256);
    attn_mma_kernel<<<NBWIN, 256, ATT_SMEM>>>(qkvb, bt, attb);
    bgemm_kernel<0,1><<<dim3(2, MBLK), 256, GM_SMEM>>>(attb, wb + WOFF_P, pb, nullptr, prjb, NTOK, 256, 256);
    resid_ln2_kernel<<<NTOK/16, 256>>>(x, prjb, n2g, n2b, x1, mb);
    bgemm_kernel<1,1><<<dim3(8, MBLK), 256, GM_SMEM>>>(mb, wb + WOFF_F1, f1b, nullptr, f1buf, NTOK, 1024, 256);
    bgemm_kernel<2,0><<<dim3(2, MBLK), 256, GM_SMEM>>>(f1buf, wb + WOFF_F2, f2b, x1, out, NTOK, 256, 1024);
}

// round 13
// speedup vs baseline: 1.0568x; 1.0568x over previous
#include <cuda_runtime.h>
#include <cuda_bf16.h>
#include <math.h>
#include <stdint.h>

// ---------------- problem constants ----------------
#define BSZ   64
#define LSEQ  2688
#define CDIM  256
#define WWIN  42
#define SSH   21
#define NHEAD 8
#define HDIM  32
#define NWIN  64
#define MLPH  1024
#define NTOK  (BSZ*LSEQ)    // 172032
#define NBWIN (BSZ*NWIN)    // 4096

typedef __nv_bfloat16  bf16;
typedef __nv_bfloat162 bf162;

// ---------------- scratch ----------------
__device__ bf16  gb_h0 [(size_t)NTOK*CDIM];
__device__ bf16  gb_qkv[(size_t)NTOK*3*CDIM];
__device__ bf16  gb_att[(size_t)NTOK*CDIM];
__device__ bf16  gb_prj[(size_t)NTOK*CDIM];
__device__ float g_x1  [(size_t)NTOK*CDIM];
__device__ bf16  gb_m  [(size_t)NTOK*CDIM];
__device__ bf16  gb_f1 [(size_t)NTOK*MLPH];
#define WOFF_QKV 0
#define WOFF_P   196608
#define WOFF_F1  262144
#define WOFF_F2  524288
__device__ bf16  gb_w  [786432];

// ------- merged fp32 -> bf16 weight convert (all 4 weights, 1 launch) -----
__global__ __launch_bounds__(256) void cvt_all_kernel(
    const float4* __restrict__ s0, const float4* __restrict__ s1,
    const float4* __restrict__ s2, const float4* __restrict__ s3,
    bf16* __restrict__ wb)
{
    int i = blockIdx.x*256 + threadIdx.x;   // 0 .. 196607
    const float4* src;
    bf162* dst;
    if (i < 49152)        { src = s0 + i;            dst = (bf162*)(wb + WOFF_QKV) + 2*i; }
    else if (i < 65536)   { int j = i - 49152;  src = s1 + j; dst = (bf162*)(wb + WOFF_P)  + 2*j; }
    else if (i < 131072)  { int j = i - 65536;  src = s2 + j; dst = (bf162*)(wb + WOFF_F1) + 2*j; }
    else                  { int j = i - 131072; src = s3 + j; dst = (bf162*)(wb + WOFF_F2) + 2*j; }
    float4 v = *src;
    dst[0] = bf162{__float2bfloat16(v.x), __float2bfloat16(v.y)};
    dst[1] = bf162{__float2bfloat16(v.z), __float2bfloat16(v.w)};
}

// ---------------- LayerNorm (+cyclic shift) -> bf16, 2 tokens/warp ------
__global__ __launch_bounds__(256) void ln_roll_kernel(
    const float* __restrict__ x, const float* __restrict__ g,
    const float* __restrict__ b, bf16* __restrict__ out)
{
    const int warp = threadIdx.x >> 5, lane = threadIdx.x & 31;
    const int tok0 = blockIdx.x * 16 + warp * 2;

    int biA = tok0 / LSEQ, lA = tok0 - biA*LSEQ;
    int tokB = tok0 + 1;
    int biB = tokB / LSEQ, lB = tokB - biB*LSEQ;
    int srcA = biA * LSEQ + (lA + SSH) % LSEQ;
    int srcB = biB * LSEQ + (lB + SSH) % LSEQ;

    const float4* xrA = (const float4*)(x + (size_t)srcA * CDIM);
    const float4* xrB = (const float4*)(x + (size_t)srcB * CDIM);
    float4 a0 = xrA[lane], a1 = xrA[lane + 32];
    float4 c0 = xrB[lane], c1 = xrB[lane + 32];

    float sA  = a0.x+a0.y+a0.z+a0.w + a1.x+a1.y+a1.z+a1.w;
    float ssA = a0.x*a0.x+a0.y*a0.y+a0.z*a0.z+a0.w*a0.w
              + a1.x*a1.x+a1.y*a1.y+a1.z*a1.z+a1.w*a1.w;
    float sB  = c0.x+c0.y+c0.z+c0.w + c1.x+c1.y+c1.z+c1.w;
    float ssB = c0.x*c0.x+c0.y*c0.y+c0.z*c0.z+c0.w*c0.w
              + c1.x*c1.x+c1.y*c1.y+c1.z*c1.z+c1.w*c1.w;
    #pragma unroll
    for (int o = 16; o; o >>= 1) {
        sA  += __shfl_xor_sync(0xffffffffu, sA,  o);
        ssA += __shfl_xor_sync(0xffffffffu, ssA, o);
        sB  += __shfl_xor_sync(0xffffffffu, sB,  o);
        ssB += __shfl_xor_sync(0xffffffffu, ssB, o);
    }
    float mA = sA * (1.0f/CDIM), mB = sB * (1.0f/CDIM);
    float iA = rsqrtf(ssA*(1.0f/CDIM) - mA*mA + 1e-5f);
    float iB = rsqrtf(ssB*(1.0f/CDIM) - mB*mB + 1e-5f);

    float4 g0 = ((const float4*)g)[lane], g1 = ((const float4*)g)[lane+32];
    float4 b0 = ((const float4*)b)[lane], b1 = ((const float4*)b)[lane+32];

    bf162* oA = (bf162*)(out + (size_t)tok0 * CDIM);
    bf162* oB = (bf162*)(out + (size_t)tokB * CDIM);
    oA[2*lane]      = bf162{__float2bfloat16((a0.x-mA)*iA*g0.x+b0.x),
                            __float2bfloat16((a0.y-mA)*iA*g0.y+b0.y)};
    oA[2*lane+1]    = bf162{__float2bfloat16((a0.z-mA)*iA*g0.z+b0.z),
                            __float2bfloat16((a0.w-mA)*iA*g0.w+b0.w)};
    oA[64+2*lane]   = bf162{__float2bfloat16((a1.x-mA)*iA*g1.x+b1.x),
                            __float2bfloat16((a1.y-mA)*iA*g1.y+b1.y)};
    oA[64+2*lane+1] = bf162{__float2bfloat16((a1.z-mA)*iA*g1.z+b1.z),
                            __float2bfloat16((a1.w-mA)*iA*g1.w+b1.w)};
    oB[2*lane]      = bf162{__float2bfloat16((c0.x-mB)*iB*g0.x+b0.x),
                            __float2bfloat16((c0.y-mB)*iB*g0.y+b0.y)};
    oB[2*lane+1]    = bf162{__float2bfloat16((c0.z-mB)*iB*g0.z+b0.z),
                            __float2bfloat16((c0.w-mB)*iB*g0.w+b0.w)};
    oB[64+2*lane]   = bf162{__float2bfloat16((c1.x-mB)*iB*g1.x+b1.x),
                            __float2bfloat16((c1.y-mB)*iB*g1.y+b1.y)};
    oB[64+2*lane+1] = bf162{__float2bfloat16((c1.z-mB)*iB*g1.z+b1.z),
                            __float2bfloat16((c1.w-mB)*iB*g1.w+b1.w)};
}

// --- residual (reverse shift, bf16 proj) + LN2, 2 tokens/warp ---------
__global__ __launch_bounds__(256) void resid_ln2_kernel(
    const float* __restrict__ x,  const bf16* __restrict__ po,
    const float* __restrict__ g,  const float* __restrict__ b,
    float* __restrict__ x1, bf16* __restrict__ m)
{
    const int warp = threadIdx.x >> 5, lane = threadIdx.x & 31;
    const int tok0 = blockIdx.x * 16 + warp * 2;
    const int tokB = tok0 + 1;

    int biA = tok0 / LSEQ, lA = tok0 - biA*LSEQ;
    int biB = tokB / LSEQ, lB = tokB - biB*LSEQ;
    int srcA = biA * LSEQ + (lA - SSH + LSEQ) % LSEQ;
    int srcB = biB * LSEQ + (lB - SSH + LSEQ) % LSEQ;

    const float4* xrA = (const float4*)(x + (size_t)tok0 * CDIM);
    const float4* xrB = (const float4*)(x + (size_t)tokB * CDIM);
    const bf162* prA = (const bf162*)(po + (size_t)srcA * CDIM);
    const bf162* prB = (const bf162*)(po + (size_t)srcB * CDIM);

    float4 a0 = xrA[lane], a1 = xrA[lane+32];
    float4 c0 = xrB[lane], c1 = xrB[lane+32];
    float2 pA00 = __bfloat1622float2(prA[2*lane]);
    float2 pA01 = __bfloat1622float2(prA[2*lane+1]);
    float2 pA10 = __bfloat1622float2(prA[64+2*lane]);
    float2 pA11 = __bfloat1622float2(prA[64+2*lane+1]);
    float2 pB00 = __bfloat1622float2(prB[2*lane]);
    float2 pB01 = __bfloat1622float2(prB[2*lane+1]);
    float2 pB10 = __bfloat1622float2(prB[64+2*lane]);
    float2 pB11 = __bfloat1622float2(prB[64+2*lane+1]);

    float4 vA0, vA1, vB0, vB1;
    vA0.x=a0.x+pA00.x; vA0.y=a0.y+pA00.y; vA0.z=a0.z+pA01.x; vA0.w=a0.w+pA01.y;
    vA1.x=a1.x+pA10.x; vA1.y=a1.y+pA10.y; vA1.z=a1.z+pA11.x; vA1.w=a1.w+pA11.y;
    vB0.x=c0.x+pB00.x; vB0.y=c0.y+pB00.y; vB0.z=c0.z+pB01.x; vB0.w=c0.w+pB01.y;
    vB1.x=c1.x+pB10.x; vB1.y=c1.y+pB10.y; vB1.z=c1.z+pB11.x; vB1.w=c1.w+pB11.y;

    float4* x1A = (float4*)(x1 + (size_t)tok0 * CDIM);
    float4* x1B = (float4*)(x1 + (size_t)tokB * CDIM);
    x1A[lane] = vA0; x1A[lane+32] = vA1;
    x1B[lane] = vB0; x1B[lane+32] = vB1;

    float sA  = vA0.x+vA0.y+vA0.z+vA0.w + vA1.x+vA1.y+vA1.z+vA1.w;
    float ssA = vA0.x*vA0.x+vA0.y*vA0.y+vA0.z*vA0.z+vA0.w*vA0.w
              + vA1.x*vA1.x+vA1.y*vA1.y+vA1.z*vA1.z+vA1.w*vA1.w;
    float sB  = vB0.x+vB0.y+vB0.z+vB0.w + vB1.x+vB1.y+vB1.z+vB1.w;
    float ssB = vB0.x*vB0.x+vB0.y*vB0.y+vB0.z*vB0.z+vB0.w*vB0.w
              + vB1.x*vB1.x+vB1.y*vB1.y+vB1.z*vB1.z+vB1.w*vB1.w;
    #pragma unroll
    for (int o = 16; o; o >>= 1) {
        sA  += __shfl_xor_sync(0xffffffffu, sA,  o);
        ssA += __shfl_xor_sync(0xffffffffu, ssA, o);
        sB  += __shfl_xor_sync(0xffffffffu, sB,  o);
        ssB += __shfl_xor_sync(0xffffffffu, ssB, o);
    }
    float mA = sA * (1.0f/CDIM), mB = sB * (1.0f/CDIM);
    float iA = rsqrtf(ssA*(1.0f/CDIM) - mA*mA + 1e-5f);
    float iB = rsqrtf(ssB*(1.0f/CDIM) - mB*mB + 1e-5f);

    float4 g0 = ((const float4*)g)[lane], g1 = ((const float4*)g)[lane+32];
    float4 b0 = ((const float4*)b)[lane], b1 = ((const float4*)b)[lane+32];

    bf162* mA_ = (bf162*)(m + (size_t)tok0 * CDIM);
    bf162* mB_ = (bf162*)(m + (size_t)tokB * CDIM);
    mA_[2*lane]      = bf162{__float2bfloat16((vA0.x-mA)*iA*g0.x+b0.x),
                             __float2bfloat16((vA0.y-mA)*iA*g0.y+b0.y)};
    mA_[2*lane+1]    = bf162{__float2bfloat16((vA0.z-mA)*iA*g0.z+b0.z),
                             __float2bfloat16((vA0.w-mA)*iA*g0.w+b0.w)};
    mA_[64+2*lane]   = bf162{__float2bfloat16((vA1.x-mA)*iA*g1.x+b1.x),
                             __float2bfloat16((vA1.y-mA)*iA*g1.y+b1.y)};
    mA_[64+2*lane+1] = bf162{__float2bfloat16((vA1.z-mA)*iA*g1.z+b1.z),
                             __float2bfloat16((vA1.w-mA)*iA*g1.w+b1.w)};
    mB_[2*lane]      = bf162{__float2bfloat16((vB0.x-mB)*iB*g0.x+b0.x),
                             __float2bfloat16((vB0.y-mB)*iB*g0.y+b0.y)};
    mB_[2*lane+1]    = bf162{__float2bfloat16((vB0.z-mB)*iB*g0.z+b0.z),
                             __float2bfloat16((vB0.w-mB)*iB*g0.w+b0.w)};
    mB_[64+2*lane]   = bf162{__float2bfloat16((vB1.x-mB)*iB*g1.x+b1.x),
                             __float2bfloat16((vB1.y-mB)*iB*g1.y+b1.y)};
    mB_[64+2*lane+1] = bf162{__float2bfloat16((vB1.z-mB)*iB*g1.z+b1.z),
                             __float2bfloat16((vB1.w-mB)*iB*g1.w+b1.w)};
}

// ---------------- mma helpers ---------------------
__device__ __forceinline__ float gelu_exact(float v) {
    return 0.5f * v * (1.0f + erff(v * 0.70710678118654752f));
}
__device__ __forceinline__ void cpasync16(uint32_t saddr, const void* g) {
    asm volatile("cp.async.cg.shared.global [%0], [%1], 16;\n" :: "r"(saddr), "l"(g));
}
__device__ __forceinline__ void ldsm_x4(uint32_t* r, uint32_t a) {
    asm volatile("ldmatrix.sync.aligned.m8n8.x4.shared.b16 {%0,%1,%2,%3}, [%4];"
        : "=r"(r[0]), "=r"(r[1]), "=r"(r[2]), "=r"(r[3]) : "r"(a));
}
__device__ __forceinline__ void ldsm_x4t(uint32_t* r, uint32_t a) {
    asm volatile("ldmatrix.sync.aligned.m8n8.x4.trans.shared.b16 {%0,%1,%2,%3}, [%4];"
        : "=r"(r[0]), "=r"(r[1]), "=r"(r[2]), "=r"(r[3]) : "r"(a));
}
__device__ __forceinline__ void mma_bf16(
    float& c0, float& c1, float& c2, float& c3,
    uint32_t a0, uint32_t a1, uint32_t a2, uint32_t a3,
    uint32_t b0, uint32_t b1)
{
    asm volatile(
        "mma.sync.aligned.m16n8k16.row.col.f32.bf16.bf16.f32 "
        "{%0,%1,%2,%3}, {%4,%5,%6,%7}, {%8,%9}, {%0,%1,%2,%3};\n"
        : "+f"(c0), "+f"(c1), "+f"(c2), "+f"(c3)
        : "r"(a0), "r"(a1), "r"(a2), "r"(a3), "r"(b0), "r"(b1));
}
__device__ __forceinline__ uint32_t packbf(float x, float y) {
    bf162 p = bf162{__float2bfloat16(x), __float2bfloat16(y)};
    return *(uint32_t*)&p;
}

// ------- bf16 GEMM: 128x128 block, warp 64x32, 4-stage cp.async (R8) ----
#define BKK   32
#define LDAg  40
#define LDBg  136
#define ASZ   (128*LDAg*2)
#define BSZB  (BKK*LDBg*2)
#define STG   (ASZ + BSZB)
#define NSTG  4
#define GM_SMEM (NSTG*STG)

template<int EPI, int OUTBF>
__global__ __launch_bounds__(256) void bgemm_kernel(
    const bf16* __restrict__ A, const bf16* __restrict__ Bw,
    const float* __restrict__ bias, const float* __restrict__ res,
    void* __restrict__ Cv, int M, int N, int K)
{
    extern __shared__ __align__(16) char gsm[];
    const uint32_t smBase = (uint32_t)__cvta_generic_to_shared(gsm);

    const int tid  = threadIdx.x;
    const int warp = tid >> 5, lane = tid & 31;
    const int wm  = (warp >> 2) * 64;
    const int wn  = (warp & 3) * 32;
    const int grp = lane & 3;
    const int qid = lane >> 2;

    const int arow = tid >> 1, acol = (tid & 1) * 16;
    const int brow = tid >> 3, bcol = (tid & 7) * 16;
    const bf16* Ag = A  + (size_t)(blockIdx.y*128 + arow) * K + acol;
    const bf16* Bg = Bw + (size_t)brow * N + blockIdx.x*128 + bcol;

    const uint32_t asOff = (uint32_t)(arow*LDAg + acol) * 2;
    const uint32_t bsOff = (uint32_t)(brow*LDBg + bcol) * 2 + ASZ;

    float acc[4][4][4];
    #pragma unroll
    for (int i = 0; i < 4; i++)
        #pragma unroll
        for (int j = 0; j < 4; j++)
            #pragma unroll
            for (int t = 0; t < 4; t++) acc[i][j][t] = 0.0f;

    const int NIT = K / BKK;

    #pragma unroll
    for (int s = 0; s < NSTG-1; s++) {
        const int k0 = s * BKK;
        if (s < NIT) {
            uint32_t st = smBase + s*STG;
            cpasync16(st + asOff,      Ag + k0);
            cpasync16(st + asOff + 16, Ag + k0 + 8);
            cpasync16(st + bsOff,      Bg + (size_t)k0*N);
            cpasync16(st + bsOff + 16, Bg + (size_t)k0*N + 8);
        }
        asm volatile("cp.async.commit_group;\n");
    }

    int buf = 0;
    for (int it = 0; it < NIT; it++) {
        asm volatile("cp.async.wait_group 2;\n");
        __syncthreads();

        if (it + NSTG - 1 < NIT) {
            const int k0 = (it + NSTG - 1) * BKK;
            int nb = (buf + NSTG - 1) & (NSTG - 1);
            uint32_t st = smBase + nb*STG;
            cpasync16(st + asOff,      Ag + k0);
            cpasync16(st + asOff + 16, Ag + k0 + 8);
            cpasync16(st + bsOff,      Bg + (size_t)k0*N);
            cpasync16(st + bsOff + 16, Bg + (size_t)k0*N + 8);
        }
        asm volatile("cp.async.commit_group;\n");

        uint32_t asB = smBase + buf*STG;
        uint32_t bsB = asB + ASZ;

        #pragma unroll
        for (int ks = 0; ks < 2; ks++) {
            const int kb = ks * 16;
            uint32_t af[4][4];
            #pragma unroll
            for (int mi = 0; mi < 4; mi++) {
                int row = wm + mi*16 + (lane & 15);
                ldsm_x4(af[mi], asB + ((uint32_t)(row*LDAg + kb + (lane >> 4)*8)) * 2);
            }
            uint32_t bfr[2][4];
            #pragma unroll
            for (int gj = 0; gj < 2; gj++) {
                int krow = kb + (lane & 7) + ((lane >> 3) & 1) * 8;
                int col  = wn + gj*16 + (lane >> 4) * 8;
                ldsm_x4t(bfr[gj], bsB + ((uint32_t)(krow*LDBg + col)) * 2);
            }
            #pragma unroll
            for (int mi = 0; mi < 4; mi++)
                #pragma unroll
                for (int nj = 0; nj < 4; nj++)
                    mma_bf16(acc[mi][nj][0], acc[mi][nj][1],
                             acc[mi][nj][2], acc[mi][nj][3],
                             af[mi][0], af[mi][1], af[mi][2], af[mi][3],
                             bfr[nj >> 1][(nj & 1)*2], bfr[nj >> 1][(nj & 1)*2 + 1]);
        }
        buf = (buf + 1) & (NSTG - 1);
    }

    const int row0 = blockIdx.y*128 + wm;
    const int col0 = blockIdx.x*128 + wn;
    #pragma unroll
    for (int mi = 0; mi < 4; mi++) {
        #pragma unroll
        for (int nj = 0; nj < 4; nj++) {
            int c = col0 + nj*8 + grp*2;
            float bv0 = bias[c], bv1 = bias[c+1];
            #pragma unroll
            for (int half = 0; half < 2; half++) {
                int r = row0 + mi*16 + qid + half*8;
                float v0 = acc[mi][nj][half*2+0] + bv0;
                float v1 = acc[mi][nj][half*2+1] + bv1;
                size_t off = (size_t)r * N + c;
                if (EPI == 1) { v0 = gelu_exact(v0); v1 = gelu_exact(v1); }
                if (EPI == 2) { v0 += res[off]; v1 += res[off+1]; }
                if (OUTBF) {
                    bf162 o = {__float2bfloat16(v0), __float2bfloat16(v1)};
                    *(bf162*)((bf16*)Cv + off) = o;
                } else {
                    float2 o = {v0, v1};
                    *(float2*)((float*)Cv + off) = o;
                }
            }
        }
    }
}

// ============ tensor-core windowed attention (cp.async staging) ========
#define APAD 40
#define ATT_SMEM (3*8*48*APAD*2 + 8*84*4)

__global__ __launch_bounds__(256) void attn_mma_kernel(
    const bf16* __restrict__ qkv, const float* __restrict__ bias_table,
    bf16* __restrict__ out)
{
    extern __shared__ __align__(16) char smraw[];
    bf16* sq = (bf16*)smraw;
    bf16* sk = sq + 8*48*APAD;
    bf16* sv = sk + 8*48*APAD;
    float* sb = (float*)(sv + 8*48*APAD);

    const int w = blockIdx.x;
    const int tid = threadIdx.x, warp = tid >> 5, lane = tid & 31;

    const uint32_t sqA = (uint32_t)__cvta_generic_to_shared(sq);
    const uint32_t skA = (uint32_t)__cvta_generic_to_shared(sk);
    const uint32_t svA = (uint32_t)__cvta_generic_to_shared(sv);

    // ---- staging via cp.async: no LDG->reg->STS round trip ----
    const uint4* src = (const uint4*)(qkv + (size_t)w * WWIN * 768);
    {
        int c = tid;
        int t = tid / 96, r = tid - t*96;
        while (c < WWIN*96) {
            int kind = r >> 5;
            int hh   = (r & 31) >> 2;
            int d8   = r & 3;
            uint32_t base = (kind == 0 ? sqA : (kind == 1 ? skA : svA));
            uint32_t dst  = base + (uint32_t)((hh*48 + t)*APAD + d8*8) * 2;
            cpasync16(dst, src + c);
            c += 256; t += 2; r += 64;
            if (r >= 96) { r -= 96; t += 1; }
        }
    }
    asm volatile("cp.async.commit_group;\n");
    // zero pad rows 42..47 (plain STS, disjoint from cp.async targets)
    for (int c = tid; c < 8*6*4; c += 256) {
        int hh = c / 24, r6 = (c / 4) % 6, d8 = c & 3;
        uint4 z = {0,0,0,0};
        *(uint4*)(sq + (hh*48 + 42 + r6)*APAD + d8*8) = z;
        *(uint4*)(sk + (hh*48 + 42 + r6)*APAD + d8*8) = z;
        *(uint4*)(sv + (hh*48 + 42 + r6)*APAD + d8*8) = z;
    }
    for (int c = tid; c < 83*8; c += 256) {
        int d = c >> 3, hh = c & 7;
        sb[hh*84 + d] = bias_table[d*8 + hh];
    }
    asm volatile("cp.async.wait_group 0;\n");
    __syncthreads();

    const int h = warp;
    const uint32_t qb = sqA + (uint32_t)(h*48*APAD)*2;
    const uint32_t kb = skA + (uint32_t)(h*48*APAD)*2;
    const uint32_t vb = svA + (uint32_t)(h*48*APAD)*2;
    const float* bh = sb + h*84;
    const bool lastw = ((w & (NWIN-1)) == NWIN-1);

    float s[3][6][4];
    #pragma unroll
    for (int i = 0; i < 3; i++)
        #pragma unroll
        for (int j = 0; j < 6; j++)
            #pragma unroll
            for (int t = 0; t < 4; t++) s[i][j][t] = 0.0f;

    #pragma unroll
    for (int kt = 0; kt < 2; kt++) {
        uint32_t af[3][4], bfr[3][4];
        #pragma unroll
        for (int mi = 0; mi < 3; mi++) {
            int row = mi*16 + (lane & 15);
            ldsm_x4(af[mi], qb + ((uint32_t)(row*APAD + kt*16 + (lane >> 4)*8))*2);
        }
        #pragma unroll
        for (int np = 0; np < 3; np++) {
            int row = np*16 + (lane >> 4)*8 + (lane & 7);
            int col = kt*16 + ((lane >> 3) & 1)*8;
            ldsm_x4(bfr[np], kb + ((uint32_t)(row*APAD + col))*2);
        }
        #pragma unroll
        for (int mi = 0; mi < 3; mi++)
            #pragma unroll
            for (int nj = 0; nj < 6; nj++)
                mma_bf16(s[mi][nj][0], s[mi][nj][1], s[mi][nj][2], s[mi][nj][3],
                         af[mi][0], af[mi][1], af[mi][2], af[mi][3],
                         bfr[nj >> 1][(nj & 1)*2], bfr[nj >> 1][(nj & 1)*2 + 1]);
    }

    const int rA0 = lane >> 2;
    const int colb = (lane & 3)*2;
    #pragma unroll
    for (int mi = 0; mi < 3; mi++) {
        int rA = mi*16 + rA0, rB = rA + 8;
        #pragma unroll
        for (int nj = 0; nj < 6; nj++) {
            int c0 = nj*8 + colb, c1 = c0 + 1;
            int dA0 = min(max(c0 - rA + 41, 0), 82);
            int dA1 = min(max(c1 - rA + 41, 0), 82);
            int dB0 = min(max(c0 - rB + 41, 0), 82);
            int dB1 = min(max(c1 - rB + 41, 0), 82);
            float v0 = s[mi][nj][0]*0.17677669529663688f + bh[dA0];
            float v1 = s[mi][nj][1]*0.17677669529663688f + bh[dA1];
            if (lastw && ((rA < SSH) != (c0 < SSH))) v0 -= 100.0f;
            if (lastw && ((rA < SSH) != (c1 < SSH))) v1 -= 100.0f;
            if (c0 >= WWIN) v0 = -1e30f;
            if (c1 >= WWIN) v1 = -1e30f;
            float v2 = s[mi][nj][2]*0.17677669529663688f + bh[dB0];
            float v3 = s[mi][nj][3]*0.17677669529663688f + bh[dB1];
            if (lastw && ((rB < SSH) != (c0 < SSH))) v2 -= 100.0f;
            if (lastw && ((rB < SSH) != (c1 < SSH))) v3 -= 100.0f;
            if (c0 >= WWIN) v2 = -1e30f;
            if (c1 >= WWIN) v3 = -1e30f;
            s[mi][nj][0] = v0; s[mi][nj][1] = v1;
            s[mi][nj][2] = v2; s[mi][nj][3] = v3;
        }
        float mxA = -1e30f, mxB = -1e30f;
        #pragma unroll
        for (int nj = 0; nj < 6; nj++) {
            mxA = fmaxf(mxA, fmaxf(s[mi][nj][0], s[mi][nj][1]));
            mxB = fmaxf(mxB, fmaxf(s[mi][nj][2], s[mi][nj][3]));
        }
        mxA = fmaxf(mxA, __shfl_xor_sync(0xffffffffu, mxA, 1));
        mxA = fmaxf(mxA, __shfl_xor_sync(0xffffffffu, mxA, 2));
        mxB = fmaxf(mxB, __shfl_xor_sync(0xffffffffu, mxB, 1));
        mxB = fmaxf(mxB, __shfl_xor_sync(0xffffffffu, mxB, 2));
        float smA = 0.0f, smB = 0.0f;
        #pragma unroll
        for (int nj = 0; nj < 6; nj++) {
            float e0 = __expf(s[mi][nj][0] - mxA);
            float e1 = __expf(s[mi][nj][1] - mxA);
            float e2 = __expf(s[mi][nj][2] - mxB);
            float e3 = __expf(s[mi][nj][3] - mxB);
            s[mi][nj][0] = e0; s[mi][nj][1] = e1;
            s[mi][nj][2] = e2; s[mi][nj][3] = e3;
            smA += e0 + e1; smB += e2 + e3;
        }
        smA += __shfl_xor_sync(0xffffffffu, smA, 1);
        smA += __shfl_xor_sync(0xffffffffu, smA, 2);
        smB += __shfl_xor_sync(0xffffffffu, smB, 1);
        smB += __shfl_xor_sync(0xffffffffu, smB, 2);
        float rAi = 1.0f / smA, rBi = 1.0f / smB;
        #pragma unroll
        for (int nj = 0; nj < 6; nj++) {
            s[mi][nj][0] *= rAi; s[mi][nj][1] *= rAi;
            s[mi][nj][2] *= rBi; s[mi][nj][3] *= rBi;
        }
    }

    float o[3][4][4];
    #pragma unroll
    for (int i = 0; i < 3; i++)
        #pragma unroll
        for (int j = 0; j < 4; j++)
            #pragma unroll
            for (int t = 0; t < 4; t++) o[i][j][t] = 0.0f;

    #pragma unroll
    for (int kt = 0; kt < 3; kt++) {
        uint32_t bfr[2][4];
        #pragma unroll
        for (int gj = 0; gj < 2; gj++) {
            int krow = kt*16 + (lane & 7) + ((lane >> 3) & 1)*8;
            int col  = gj*16 + (lane >> 4)*8;
            ldsm_x4t(bfr[gj], vb + ((uint32_t)(krow*APAD + col))*2);
        }
        #pragma unroll
        for (int mi = 0; mi < 3; mi++) {
            uint32_t a0 = packbf(s[mi][2*kt][0],   s[mi][2*kt][1]);
            uint32_t a1 = packbf(s[mi][2*kt][2],   s[mi][2*kt][3]);
            uint32_t a2 = packbf(s[mi][2*kt+1][0], s[mi][2*kt+1][1]);
            uint32_t a3 = packbf(s[mi][2*kt+1][2], s[mi][2*kt+1][3]);
            #pragma unroll
            for (int nj = 0; nj < 4; nj++)
                mma_bf16(o[mi][nj][0], o[mi][nj][1], o[mi][nj][2], o[mi][nj][3],
                         a0, a1, a2, a3,
                         bfr[nj >> 1][(nj & 1)*2], bfr[nj >> 1][(nj & 1)*2 + 1]);
        }
    }

    #pragma unroll
    for (int mi = 0; mi < 3; mi++) {
        int rA = mi*16 + rA0, rB = rA + 8;
        #pragma unroll
        for (int nj = 0; nj < 4; nj++) {
            int c = nj*8 + colb;
            if (rA < WWIN) {
                bf162 p = bf162{__float2bfloat16(o[mi][nj][0]), __float2bfloat16(o[mi][nj][1])};
                *(bf162*)(out + ((size_t)w*WWIN + rA)*CDIM + h*HDIM + c) = p;
            }
            if (rB < WWIN) {
                bf162 p = bf162{__float2bfloat16(o[mi][nj][2]), __float2bfloat16(o[mi][nj][3])};
                *(bf162*)(out + ((size_t)w*WWIN + rB)*CDIM + h*HDIM + c) = p;
            }
        }
    }
}

// ---------------- host-side launch --------------------------
extern "C" void kernel_launch(void* const* d_in, const int* in_sizes, int n_in,
                              void* d_out, int out_size)
{
    const float* x     = (const float*)d_in[0];
    const float* n1g   = (const float*)d_in[1];
    const float* n1b   = (const float*)d_in[2];
    const float* qkv_w = (const float*)d_in[3];
    const float* qkv_b = (const float*)d_in[4];
    const float* bt    = (const float*)d_in[5];
    const float* pw    = (const float*)d_in[6];
    const float* pb    = (const float*)d_in[7];
    const float* n2g   = (const float*)d_in[8];
    const float* n2b   = (const float*)d_in[9];
    const float* f1w   = (const float*)d_in[10];
    const float* f1b   = (const float*)d_in[11];
    const float* f2w   = (const float*)d_in[12];
    const float* f2b   = (const float*)d_in[13];
    float* out = (float*)d_out;

    bf16 *h0b, *qkvb, *attb, *prjb, *mb, *f1buf, *wb;
    float *x1;
    cudaGetSymbolAddress((void**)&h0b,  gb_h0);
    cudaGetSymbolAddress((void**)&qkvb, gb_qkv);
    cudaGetSymbolAddress((void**)&attb, gb_att);
    cudaGetSymbolAddress((void**)&prjb, gb_prj);
    cudaGetSymbolAddress((void**)&x1,   g_x1);
    cudaGetSymbolAddress((void**)&mb,   gb_m);
    cudaGetSymbolAddress((void**)&f1buf,gb_f1);
    cudaGetSymbolAddress((void**)&wb,   gb_w);

    cudaFuncSetAttribute(attn_mma_kernel,
                         cudaFuncAttributeMaxDynamicSharedMemorySize, ATT_SMEM);
    cudaFuncSetAttribute(bgemm_kernel<0,1>,
                         cudaFuncAttributeMaxDynamicSharedMemorySize, GM_SMEM);
    cudaFuncSetAttribute(bgemm_kernel<1,1>,
                         cudaFuncAttributeMaxDynamicSharedMemorySize, GM_SMEM);
    cudaFuncSetAttribute(bgemm_kernel<2,0>,
                         cudaFuncAttributeMaxDynamicSharedMemorySize, GM_SMEM);

    cvt_all_kernel<<<768, 256>>>((const float4*)qkv_w, (const float4*)pw,
                                 (const float4*)f1w,   (const float4*)f2w, wb);

    const int MBLK = NTOK / 128;   // 1344

    ln_roll_kernel<<<NTOK/16, 256>>>(x, n1g, n1b, h0b);
    bgemm_kernel<0,1><<<dim3(6, MBLK), 256, GM_SMEM>>>(h0b, wb + WOFF_QKV, qkv_b, nullptr, qkvb, NTOK, 768, 256);
    attn_mma_kernel<<<NBWIN, 256, ATT_SMEM>>>(qkvb, bt, attb);
    bgemm_kernel<0,1><<<dim3(2, MBLK), 256, GM_SMEM>>>(attb, wb + WOFF_P, pb, nullptr, prjb, NTOK, 256, 256);
    resid_ln2_kernel<<<NTOK/16, 256>>>(x, prjb, n2g, n2b, x1, mb);
    bgemm_kernel<1,1><<<dim3(8, MBLK), 256, GM_SMEM>>>(mb, wb + WOFF_F1, f1b, nullptr, f1buf, NTOK, 1024, 256);
    bgemm_kernel<2,0><<<dim3(2, MBLK), 256, GM_SMEM>>>(f1buf, wb + WOFF_F2, f2b, x1, out, NTOK, 256, 1024);
}

// round 14
// speedup vs baseline: 1.0664x; 1.0091x over previous
#include <cuda_runtime.h>
#include <cuda_bf16.h>
#include <math.h>
#include <stdint.h>

// ---------------- problem constants ----------------
#define BSZ   64
#define LSEQ  2688
#define CDIM  256
#define WWIN  42
#define SSH   21
#define NHEAD 8
#define HDIM  32
#define NWIN  64
#define MLPH  1024
#define NTOK  (BSZ*LSEQ)    // 172032
#define NBWIN (BSZ*NWIN)    // 4096

typedef __nv_bfloat16  bf16;
typedef __nv_bfloat162 bf162;

// ---------------- scratch ----------------
__device__ bf16  gb_h0 [(size_t)NTOK*CDIM];
__device__ bf16  gb_qkv[(size_t)NTOK*3*CDIM];
__device__ bf16  gb_att[(size_t)NTOK*CDIM];
__device__ bf16  gb_prj[(size_t)NTOK*CDIM];
__device__ bf16  gb_m  [(size_t)NTOK*CDIM];
__device__ bf16  gb_f1 [(size_t)NTOK*MLPH];
#define WOFF_QKV 0
#define WOFF_P   196608
#define WOFF_F1  262144
#define WOFF_F2  524288
__device__ bf16  gb_w  [786432];

// ------- merged fp32 -> bf16 weight convert (all 4 weights, 1 launch) -----
__global__ __launch_bounds__(256) void cvt_all_kernel(
    const float4* __restrict__ s0, const float4* __restrict__ s1,
    const float4* __restrict__ s2, const float4* __restrict__ s3,
    bf16* __restrict__ wb)
{
    int i = blockIdx.x*256 + threadIdx.x;   // 0 .. 196607
    const float4* src;
    bf162* dst;
    if (i < 49152)        { src = s0 + i;            dst = (bf162*)(wb + WOFF_QKV) + 2*i; }
    else if (i < 65536)   { int j = i - 49152;  src = s1 + j; dst = (bf162*)(wb + WOFF_P)  + 2*j; }
    else if (i < 131072)  { int j = i - 65536;  src = s2 + j; dst = (bf162*)(wb + WOFF_F1) + 2*j; }
    else                  { int j = i - 131072; src = s3 + j; dst = (bf162*)(wb + WOFF_F2) + 2*j; }
    float4 v = *src;
    dst[0] = bf162{__float2bfloat16(v.x), __float2bfloat16(v.y)};
    dst[1] = bf162{__float2bfloat16(v.z), __float2bfloat16(v.w)};
}

// ---------------- LayerNorm (+cyclic shift) -> bf16, 2 tokens/warp ------
__global__ __launch_bounds__(256) void ln_roll_kernel(
    const float* __restrict__ x, const float* __restrict__ g,
    const float* __restrict__ b, bf16* __restrict__ out)
{
    const int warp = threadIdx.x >> 5, lane = threadIdx.x & 31;
    const int tok0 = blockIdx.x * 16 + warp * 2;

    int biA = tok0 / LSEQ, lA = tok0 - biA*LSEQ;
    int tokB = tok0 + 1;
    int biB = tokB / LSEQ, lB = tokB - biB*LSEQ;
    int srcA = biA * LSEQ + (lA + SSH) % LSEQ;
    int srcB = biB * LSEQ + (lB + SSH) % LSEQ;

    const float4* xrA = (const float4*)(x + (size_t)srcA * CDIM);
    const float4* xrB = (const float4*)(x + (size_t)srcB * CDIM);
    float4 a0 = xrA[lane], a1 = xrA[lane + 32];
    float4 c0 = xrB[lane], c1 = xrB[lane + 32];

    float sA  = a0.x+a0.y+a0.z+a0.w + a1.x+a1.y+a1.z+a1.w;
    float ssA = a0.x*a0.x+a0.y*a0.y+a0.z*a0.z+a0.w*a0.w
              + a1.x*a1.x+a1.y*a1.y+a1.z*a1.z+a1.w*a1.w;
    float sB  = c0.x+c0.y+c0.z+c0.w + c1.x+c1.y+c1.z+c1.w;
    float ssB = c0.x*c0.x+c0.y*c0.y+c0.z*c0.z+c0.w*c0.w
              + c1.x*c1.x+c1.y*c1.y+c1.z*c1.z+c1.w*c1.w;
    #pragma unroll
    for (int o = 16; o; o >>= 1) {
        sA  += __shfl_xor_sync(0xffffffffu, sA,  o);
        ssA += __shfl_xor_sync(0xffffffffu, ssA, o);
        sB  += __shfl_xor_sync(0xffffffffu, sB,  o);
        ssB += __shfl_xor_sync(0xffffffffu, ssB, o);
    }
    float mA = sA * (1.0f/CDIM), mB = sB * (1.0f/CDIM);
    float iA = rsqrtf(ssA*(1.0f/CDIM) - mA*mA + 1e-5f);
    float iB = rsqrtf(ssB*(1.0f/CDIM) - mB*mB + 1e-5f);

    float4 g0 = ((const float4*)g)[lane], g1 = ((const float4*)g)[lane+32];
    float4 b0 = ((const float4*)b)[lane], b1 = ((const float4*)b)[lane+32];

    bf162* oA = (bf162*)(out + (size_t)tok0 * CDIM);
    bf162* oB = (bf162*)(out + (size_t)tokB * CDIM);
    oA[2*lane]      = bf162{__float2bfloat16((a0.x-mA)*iA*g0.x+b0.x),
                            __float2bfloat16((a0.y-mA)*iA*g0.y+b0.y)};
    oA[2*lane+1]    = bf162{__float2bfloat16((a0.z-mA)*iA*g0.z+b0.z),
                            __float2bfloat16((a0.w-mA)*iA*g0.w+b0.w)};
    oA[64+2*lane]   = bf162{__float2bfloat16((a1.x-mA)*iA*g1.x+b1.x),
                            __float2bfloat16((a1.y-mA)*iA*g1.y+b1.y)};
    oA[64+2*lane+1] = bf162{__float2bfloat16((a1.z-mA)*iA*g1.z+b1.z),
                            __float2bfloat16((a1.w-mA)*iA*g1.w+b1.w)};
    oB[2*lane]      = bf162{__float2bfloat16((c0.x-mB)*iB*g0.x+b0.x),
                            __float2bfloat16((c0.y-mB)*iB*g0.y+b0.y)};
    oB[2*lane+1]    = bf162{__float2bfloat16((c0.z-mB)*iB*g0.z+b0.z),
                            __float2bfloat16((c0.w-mB)*iB*g0.w+b0.w)};
    oB[64+2*lane]   = bf162{__float2bfloat16((c1.x-mB)*iB*g1.x+b1.x),
                            __float2bfloat16((c1.y-mB)*iB*g1.y+b1.y)};
    oB[64+2*lane+1] = bf162{__float2bfloat16((c1.z-mB)*iB*g1.z+b1.z),
                            __float2bfloat16((c1.w-mB)*iB*g1.w+b1.w)};
}

// --- LN2 over (x + rolled prj): writes m ONLY (no x1 materialization) ----
__global__ __launch_bounds__(256) void resid_ln2_kernel(
    const float* __restrict__ x,  const bf16* __restrict__ po,
    const float* __restrict__ g,  const float* __restrict__ b,
    bf16* __restrict__ m)
{
    const int warp = threadIdx.x >> 5, lane = threadIdx.x & 31;
    const int tok0 = blockIdx.x * 16 + warp * 2;
    const int tokB = tok0 + 1;

    int biA = tok0 / LSEQ, lA = tok0 - biA*LSEQ;
    int biB = tokB / LSEQ, lB = tokB - biB*LSEQ;
    int srcA = biA * LSEQ + (lA - SSH + LSEQ) % LSEQ;
    int srcB = biB * LSEQ + (lB - SSH + LSEQ) % LSEQ;

    const float4* xrA = (const float4*)(x + (size_t)tok0 * CDIM);
    const float4* xrB = (const float4*)(x + (size_t)tokB * CDIM);
    const bf162* prA = (const bf162*)(po + (size_t)srcA * CDIM);
    const bf162* prB = (const bf162*)(po + (size_t)srcB * CDIM);

    float4 a0 = xrA[lane], a1 = xrA[lane+32];
    float4 c0 = xrB[lane], c1 = xrB[lane+32];
    float2 pA00 = __bfloat1622float2(prA[2*lane]);
    float2 pA01 = __bfloat1622float2(prA[2*lane+1]);
    float2 pA10 = __bfloat1622float2(prA[64+2*lane]);
    float2 pA11 = __bfloat1622float2(prA[64+2*lane+1]);
    float2 pB00 = __bfloat1622float2(prB[2*lane]);
    float2 pB01 = __bfloat1622float2(prB[2*lane+1]);
    float2 pB10 = __bfloat1622float2(prB[64+2*lane]);
    float2 pB11 = __bfloat1622float2(prB[64+2*lane+1]);

    float4 vA0, vA1, vB0, vB1;
    vA0.x=a0.x+pA00.x; vA0.y=a0.y+pA00.y; vA0.z=a0.z+pA01.x; vA0.w=a0.w+pA01.y;
    vA1.x=a1.x+pA10.x; vA1.y=a1.y+pA10.y; vA1.z=a1.z+pA11.x; vA1.w=a1.w+pA11.y;
    vB0.x=c0.x+pB00.x; vB0.y=c0.y+pB00.y; vB0.z=c0.z+pB01.x; vB0.w=c0.w+pB01.y;
    vB1.x=c1.x+pB10.x; vB1.y=c1.y+pB10.y; vB1.z=c1.z+pB11.x; vB1.w=c1.w+pB11.y;

    float sA  = vA0.x+vA0.y+vA0.z+vA0.w + vA1.x+vA1.y+vA1.z+vA1.w;
    float ssA = vA0.x*vA0.x+vA0.y*vA0.y+vA0.z*vA0.z+vA0.w*vA0.w
              + vA1.x*vA1.x+vA1.y*vA1.y+vA1.z*vA1.z+vA1.w*vA1.w;
    float sB  = vB0.x+vB0.y+vB0.z+vB0.w + vB1.x+vB1.y+vB1.z+vB1.w;
    float ssB = vB0.x*vB0.x+vB0.y*vB0.y+vB0.z*vB0.z+vB0.w*vB0.w
              + vB1.x*vB1.x+vB1.y*vB1.y+vB1.z*vB1.z+vB1.w*vB1.w;
    #pragma unroll
    for (int o = 16; o; o >>= 1) {
        sA  += __shfl_xor_sync(0xffffffffu, sA,  o);
        ssA += __shfl_xor_sync(0xffffffffu, ssA, o);
        sB  += __shfl_xor_sync(0xffffffffu, sB,  o);
        ssB += __shfl_xor_sync(0xffffffffu, ssB, o);
    }
    float mA = sA * (1.0f/CDIM), mB = sB * (1.0f/CDIM);
    float iA = rsqrtf(ssA*(1.0f/CDIM) - mA*mA + 1e-5f);
    float iB = rsqrtf(ssB*(1.0f/CDIM) - mB*mB + 1e-5f);

    float4 g0 = ((const float4*)g)[lane], g1 = ((const float4*)g)[lane+32];
    float4 b0 = ((const float4*)b)[lane], b1 = ((const float4*)b)[lane+32];

    bf162* mA_ = (bf162*)(m + (size_t)tok0 * CDIM);
    bf162* mB_ = (bf162*)(m + (size_t)tokB * CDIM);
    mA_[2*lane]      = bf162{__float2bfloat16((vA0.x-mA)*iA*g0.x+b0.x),
                             __float2bfloat16((vA0.y-mA)*iA*g0.y+b0.y)};
    mA_[2*lane+1]    = bf162{__float2bfloat16((vA0.z-mA)*iA*g0.z+b0.z),
                             __float2bfloat16((vA0.w-mA)*iA*g0.w+b0.w)};
    mA_[64+2*lane]   = bf162{__float2bfloat16((vA1.x-mA)*iA*g1.x+b1.x),
                             __float2bfloat16((vA1.y-mA)*iA*g1.y+b1.y)};
    mA_[64+2*lane+1] = bf162{__float2bfloat16((vA1.z-mA)*iA*g1.z+b1.z),
                             __float2bfloat16((vA1.w-mA)*iA*g1.w+b1.w)};
    mB_[2*lane]      = bf162{__float2bfloat16((vB0.x-mB)*iB*g0.x+b0.x),
                             __float2bfloat16((vB0.y-mB)*iB*g0.y+b0.y)};
    mB_[2*lane+1]    = bf162{__float2bfloat16((vB0.z-mB)*iB*g0.z+b0.z),
                             __float2bfloat16((vB0.w-mB)*iB*g0.w+b0.w)};
    mB_[64+2*lane]   = bf162{__float2bfloat16((vB1.x-mB)*iB*g1.x+b1.x),
                             __float2bfloat16((vB1.y-mB)*iB*g1.y+b1.y)};
    mB_[64+2*lane+1] = bf162{__float2bfloat16((vB1.z-mB)*iB*g1.z+b1.z),
                             __float2bfloat16((vB1.w-mB)*iB*g1.w+b1.w)};
}

// ---------------- mma helpers ---------------------
__device__ __forceinline__ float gelu_exact(float v) {
    return 0.5f * v * (1.0f + erff(v * 0.70710678118654752f));
}
__device__ __forceinline__ void cpasync16(uint32_t saddr, const void* g) {
    asm volatile("cp.async.cg.shared.global [%0], [%1], 16;\n" :: "r"(saddr), "l"(g));
}
__device__ __forceinline__ void ldsm_x4(uint32_t* r, uint32_t a) {
    asm volatile("ldmatrix.sync.aligned.m8n8.x4.shared.b16 {%0,%1,%2,%3}, [%4];"
        : "=r"(r[0]), "=r"(r[1]), "=r"(r[2]), "=r"(r[3]) : "r"(a));
}
__device__ __forceinline__ void ldsm_x4t(uint32_t* r, uint32_t a) {
    asm volatile("ldmatrix.sync.aligned.m8n8.x4.trans.shared.b16 {%0,%1,%2,%3}, [%4];"
        : "=r"(r[0]), "=r"(r[1]), "=r"(r[2]), "=r"(r[3]) : "r"(a));
}
__device__ __forceinline__ void mma_bf16(
    float& c0, float& c1, float& c2, float& c3,
    uint32_t a0, uint32_t a1, uint32_t a2, uint32_t a3,
    uint32_t b0, uint32_t b1)
{
    asm volatile(
        "mma.sync.aligned.m16n8k16.row.col.f32.bf16.bf16.f32 "
        "{%0,%1,%2,%3}, {%4,%5,%6,%7}, {%8,%9}, {%0,%1,%2,%3};\n"
        : "+f"(c0), "+f"(c1), "+f"(c2), "+f"(c3)
        : "r"(a0), "r"(a1), "r"(a2), "r"(a3), "r"(b0), "r"(b1));
}
__device__ __forceinline__ uint32_t packbf(float x, float y) {
    bf162 p = bf162{__float2bfloat16(x), __float2bfloat16(y)};
    return *(uint32_t*)&p;
}

// ------- bf16 GEMM: 128x128 block, warp 64x32, 4-stage cp.async ---------
// EPI: 0=+bias ; 1=+bias,GELU ; 3=+bias + (x[row] + rolled bf16 prj[row]) residual
#define BKK   32
#define LDAg  40
#define LDBg  136
#define ASZ   (128*LDAg*2)
#define BSZB  (BKK*LDBg*2)
#define STG   (ASZ + BSZB)
#define NSTG  4
#define GM_SMEM (NSTG*STG)

template<int EPI, int OUTBF>
__global__ __launch_bounds__(256) void bgemm_kernel(
    const bf16* __restrict__ A, const bf16* __restrict__ Bw,
    const float* __restrict__ bias, const float* __restrict__ resx,
    const bf16* __restrict__ resp,
    void* __restrict__ Cv, int M, int N, int K)
{
    extern __shared__ __align__(16) char gsm[];
    const uint32_t smBase = (uint32_t)__cvta_generic_to_shared(gsm);

    const int tid  = threadIdx.x;
    const int warp = tid >> 5, lane = tid & 31;
    const int wm  = (warp >> 2) * 64;
    const int wn  = (warp & 3) * 32;
    const int grp = lane & 3;
    const int qid = lane >> 2;

    const int arow = tid >> 1, acol = (tid & 1) * 16;
    const int brow = tid >> 3, bcol = (tid & 7) * 16;
    const bf16* Ag = A  + (size_t)(blockIdx.y*128 + arow) * K + acol;
    const bf16* Bg = Bw + (size_t)brow * N + blockIdx.x*128 + bcol;

    const uint32_t asOff = (uint32_t)(arow*LDAg + acol) * 2;
    const uint32_t bsOff = (uint32_t)(brow*LDBg + bcol) * 2 + ASZ;

    float acc[4][4][4];
    #pragma unroll
    for (int i = 0; i < 4; i++)
        #pragma unroll
        for (int j = 0; j < 4; j++)
            #pragma unroll
            for (int t = 0; t < 4; t++) acc[i][j][t] = 0.0f;

    const int NIT = K / BKK;

    #pragma unroll
    for (int s = 0; s < NSTG-1; s++) {
        const int k0 = s * BKK;
        if (s < NIT) {
            uint32_t st = smBase + s*STG;
            cpasync16(st + asOff,      Ag + k0);
            cpasync16(st + asOff + 16, Ag + k0 + 8);
            cpasync16(st + bsOff,      Bg + (size_t)k0*N);
            cpasync16(st + bsOff + 16, Bg + (size_t)k0*N + 8);
        }
        asm volatile("cp.async.commit_group;\n");
    }

    int buf = 0;
    for (int it = 0; it < NIT; it++) {
        asm volatile("cp.async.wait_group 2;\n");
        __syncthreads();

        if (it + NSTG - 1 < NIT) {
            const int k0 = (it + NSTG - 1) * BKK;
            int nb = (buf + NSTG - 1) & (NSTG - 1);
            uint32_t st = smBase + nb*STG;
            cpasync16(st + asOff,      Ag + k0);
            cpasync16(st + asOff + 16, Ag + k0 + 8);
            cpasync16(st + bsOff,      Bg + (size_t)k0*N);
            cpasync16(st + bsOff + 16, Bg + (size_t)k0*N + 8);
        }
        asm volatile("cp.async.commit_group;\n");

        uint32_t asB = smBase + buf*STG;
        uint32_t bsB = asB + ASZ;

        #pragma unroll
        for (int ks = 0; ks < 2; ks++) {
            const int kb = ks * 16;
            uint32_t af[4][4];
            #pragma unroll
            for (int mi = 0; mi < 4; mi++) {
                int row = wm + mi*16 + (lane & 15);
                ldsm_x4(af[mi], asB + ((uint32_t)(row*LDAg + kb + (lane >> 4)*8)) * 2);
            }
            uint32_t bfr[2][4];
            #pragma unroll
            for (int gj = 0; gj < 2; gj++) {
                int krow = kb + (lane & 7) + ((lane >> 3) & 1) * 8;
                int col  = wn + gj*16 + (lane >> 4) * 8;
                ldsm_x4t(bfr[gj], bsB + ((uint32_t)(krow*LDBg + col)) * 2);
            }
            #pragma unroll
            for (int mi = 0; mi < 4; mi++)
                #pragma unroll
                for (int nj = 0; nj < 4; nj++)
                    mma_bf16(acc[mi][nj][0], acc[mi][nj][1],
                             acc[mi][nj][2], acc[mi][nj][3],
                             af[mi][0], af[mi][1], af[mi][2], af[mi][3],
                             bfr[nj >> 1][(nj & 1)*2], bfr[nj >> 1][(nj & 1)*2 + 1]);
        }
        buf = (buf + 1) & (NSTG - 1);
    }

    const int row0 = blockIdx.y*128 + wm;
    const int col0 = blockIdx.x*128 + wn;
    #pragma unroll
    for (int mi = 0; mi < 4; mi++) {
        #pragma unroll
        for (int half = 0; half < 2; half++) {
            const int r = row0 + mi*16 + qid + half*8;
            int src = 0;
            if (EPI == 3) {
                int bi = r / LSEQ;
                int l  = r - bi*LSEQ;
                int ls = l - SSH; if (ls < 0) ls += LSEQ;
                src = bi*LSEQ + ls;
            }
            #pragma unroll
            for (int nj = 0; nj < 4; nj++) {
                int c = col0 + nj*8 + grp*2;
                float v0 = acc[mi][nj][half*2+0] + bias[c];
                float v1 = acc[mi][nj][half*2+1] + bias[c+1];
                size_t off = (size_t)r * N + c;
                if (EPI == 1) { v0 = gelu_exact(v0); v1 = gelu_exact(v1); }
                if (EPI == 3) {
                    float2 xv = *(const float2*)(resx + off);
                    float2 pv = __bfloat1622float2(*(const bf162*)(resp + (size_t)src*N + c));
                    v0 += xv.x + pv.x;
                    v1 += xv.y + pv.y;
                }
                if (OUTBF) {
                    bf162 o = {__float2bfloat16(v0), __float2bfloat16(v1)};
                    *(bf162*)((bf16*)Cv + off) = o;
                } else {
                    float2 o = {v0, v1};
                    *(float2*)((float*)Cv + off) = o;
                }
            }
        }
    }
}

// ============ tensor-core windowed attention (cp.async staging) ========
#define APAD 40
#define ATT_SMEM (3*8*48*APAD*2 + 8*84*4)

__global__ __launch_bounds__(256) void attn_mma_kernel(
    const bf16* __restrict__ qkv, const float* __restrict__ bias_table,
    bf16* __restrict__ out)
{
    extern __shared__ __align__(16) char smraw[];
    bf16* sq = (bf16*)smraw;
    bf16* sk = sq + 8*48*APAD;
    bf16* sv = sk + 8*48*APAD;
    float* sb = (float*)(sv + 8*48*APAD);

    const int w = blockIdx.x;
    const int tid = threadIdx.x, warp = tid >> 5, lane = tid & 31;

    const uint32_t sqA = (uint32_t)__cvta_generic_to_shared(sq);
    const uint32_t skA = (uint32_t)__cvta_generic_to_shared(sk);
    const uint32_t svA = (uint32_t)__cvta_generic_to_shared(sv);

    const uint4* src = (const uint4*)(qkv + (size_t)w * WWIN * 768);
    {
        int c = tid;
        int t = tid / 96, r = tid - t*96;
        while (c < WWIN*96) {
            int kind = r >> 5;
            int hh   = (r & 31) >> 2;
            int d8   = r & 3;
            uint32_t base = (kind == 0 ? sqA : (kind == 1 ? skA : svA));
            uint32_t dst  = base + (uint32_t)((hh*48 + t)*APAD + d8*8) * 2;
            cpasync16(dst, src + c);
            c += 256; t += 2; r += 64;
            if (r >= 96) { r -= 96; t += 1; }
        }
    }
    asm volatile("cp.async.commit_group;\n");
    for (int c = tid; c < 8*6*4; c += 256) {
        int hh = c / 24, r6 = (c / 4) % 6, d8 = c & 3;
        uint4 z = {0,0,0,0};
        *(uint4*)(sq + (hh*48 + 42 + r6)*APAD + d8*8) = z;
        *(uint4*)(sk + (hh*48 + 42 + r6)*APAD + d8*8) = z;
        *(uint4*)(sv + (hh*48 + 42 + r6)*APAD + d8*8) = z;
    }
    for (int c = tid; c < 83*8; c += 256) {
        int d = c >> 3, hh = c & 7;
        sb[hh*84 + d] = bias_table[d*8 + hh];
    }
    asm volatile("cp.async.wait_group 0;\n");
    __syncthreads();

    const int h = warp;
    const uint32_t qb = sqA + (uint32_t)(h*48*APAD)*2;
    const uint32_t kb = skA + (uint32_t)(h*48*APAD)*2;
    const uint32_t vb = svA + (uint32_t)(h*48*APAD)*2;
    const float* bh = sb + h*84;
    const bool lastw = ((w & (NWIN-1)) == NWIN-1);

    float s[3][6][4];
    #pragma unroll
    for (int i = 0; i < 3; i++)
        #pragma unroll
        for (int j = 0; j < 6; j++)
            #pragma unroll
            for (int t = 0; t < 4; t++) s[i][j][t] = 0.0f;

    #pragma unroll
    for (int kt = 0; kt < 2; kt++) {
        uint32_t af[3][4], bfr[3][4];
        #pragma unroll
        for (int mi = 0; mi < 3; mi++) {
            int row = mi*16 + (lane & 15);
            ldsm_x4(af[mi], qb + ((uint32_t)(row*APAD + kt*16 + (lane >> 4)*8))*2);
        }
        #pragma unroll
        for (int np = 0; np < 3; np++) {
            int row = np*16 + (lane >> 4)*8 + (lane & 7);
            int col = kt*16 + ((lane >> 3) & 1)*8;
            ldsm_x4(bfr[np], kb + ((uint32_t)(row*APAD + col))*2);
        }
        #pragma unroll
        for (int mi = 0; mi < 3; mi++)
            #pragma unroll
            for (int nj = 0; nj < 6; nj++)
                mma_bf16(s[mi][nj][0], s[mi][nj][1], s[mi][nj][2], s[mi][nj][3],
                         af[mi][0], af[mi][1], af[mi][2], af[mi][3],
                         bfr[nj >> 1][(nj & 1)*2], bfr[nj >> 1][(nj & 1)*2 + 1]);
    }

    const int rA0 = lane >> 2;
    const int colb = (lane & 3)*2;
    #pragma unroll
    for (int mi = 0; mi < 3; mi++) {
        int rA = mi*16 + rA0, rB = rA + 8;
        #pragma unroll
        for (int nj = 0; nj < 6; nj++) {
            int c0 = nj*8 + colb, c1 = c0 + 1;
            int dA0 = min(max(c0 - rA + 41, 0), 82);
            int dA1 = min(max(c1 - rA + 41, 0), 82);
            int dB0 = min(max(c0 - rB + 41, 0), 82);
            int dB1 = min(max(c1 - rB + 41, 0), 82);
            float v0 = s[mi][nj][0]*0.17677669529663688f + bh[dA0];
            float v1 = s[mi][nj][1]*0.17677669529663688f + bh[dA1];
            if (lastw && ((rA < SSH) != (c0 < SSH))) v0 -= 100.0f;
            if (lastw && ((rA < SSH) != (c1 < SSH))) v1 -= 100.0f;
            if (c0 >= WWIN) v0 = -1e30f;
            if (c1 >= WWIN) v1 = -1e30f;
            float v2 = s[mi][nj][2]*0.17677669529663688f + bh[dB0];
            float v3 = s[mi][nj][3]*0.17677669529663688f + bh[dB1];
            if (lastw && ((rB < SSH) != (c0 < SSH))) v2 -= 100.0f;
            if (lastw && ((rB < SSH) != (c1 < SSH))) v3 -= 100.0f;
            if (c0 >= WWIN) v2 = -1e30f;
            if (c1 >= WWIN) v3 = -1e30f;
            s[mi][nj][0] = v0; s[mi][nj][1] = v1;
            s[mi][nj][2] = v2; s[mi][nj][3] = v3;
        }
        float mxA = -1e30f, mxB = -1e30f;
        #pragma unroll
        for (int nj = 0; nj < 6; nj++) {
            mxA = fmaxf(mxA, fmaxf(s[mi][nj][0], s[mi][nj][1]));
            mxB = fmaxf(mxB, fmaxf(s[mi][nj][2], s[mi][nj][3]));
        }
        mxA = fmaxf(mxA, __shfl_xor_sync(0xffffffffu, mxA, 1));
        mxA = fmaxf(mxA, __shfl_xor_sync(0xffffffffu, mxA, 2));
        mxB = fmaxf(mxB, __shfl_xor_sync(0xffffffffu, mxB, 1));
        mxB = fmaxf(mxB, __shfl_xor_sync(0xffffffffu, mxB, 2));
        float smA = 0.0f, smB = 0.0f;
        #pragma unroll
        for (int nj = 0; nj < 6; nj++) {
            float e0 = __expf(s[mi][nj][0] - mxA);
            float e1 = __expf(s[mi][nj][1] - mxA);
            float e2 = __expf(s[mi][nj][2] - mxB);
            float e3 = __expf(s[mi][nj][3] - mxB);
            s[mi][nj][0] = e0; s[mi][nj][1] = e1;
            s[mi][nj][2] = e2; s[mi][nj][3] = e3;
            smA += e0 + e1; smB += e2 + e3;
        }
        smA += __shfl_xor_sync(0xffffffffu, smA, 1);
        smA += __shfl_xor_sync(0xffffffffu, smA, 2);
        smB += __shfl_xor_sync(0xffffffffu, smB, 1);
        smB += __shfl_xor_sync(0xffffffffu, smB, 2);
        float rAi = 1.0f / smA, rBi = 1.0f / smB;
        #pragma unroll
        for (int nj = 0; nj < 6; nj++) {
            s[mi][nj][0] *= rAi; s[mi][nj][1] *= rAi;
            s[mi][nj][2] *= rBi; s[mi][nj][3] *= rBi;
        }
    }

    float o[3][4][4];
    #pragma unroll
    for (int i = 0; i < 3; i++)
        #pragma unroll
        for (int j = 0; j < 4; j++)
            #pragma unroll
            for (int t = 0; t < 4; t++) o[i][j][t] = 0.0f;

    #pragma unroll
    for (int kt = 0; kt < 3; kt++) {
        uint32_t bfr[2][4];
        #pragma unroll
        for (int gj = 0; gj < 2; gj++) {
            int krow = kt*16 + (lane & 7) + ((lane >> 3) & 1)*8;
            int col  = gj*16 + (lane >> 4)*8;
            ldsm_x4t(bfr[gj], vb + ((uint32_t)(krow*APAD + col))*2);
        }
        #pragma unroll
        for (int mi = 0; mi < 3; mi++) {
            uint32_t a0 = packbf(s[mi][2*kt][0],   s[mi][2*kt][1]);
            uint32_t a1 = packbf(s[mi][2*kt][2],   s[mi][2*kt][3]);
            uint32_t a2 = packbf(s[mi][2*kt+1][0], s[mi][2*kt+1][1]);
            uint32_t a3 = packbf(s[mi][2*kt+1][2], s[mi][2*kt+1][3]);
            #pragma unroll
            for (int nj = 0; nj < 4; nj++)
                mma_bf16(o[mi][nj][0], o[mi][nj][1], o[mi][nj][2], o[mi][nj][3],
                         a0, a1, a2, a3,
                         bfr[nj >> 1][(nj & 1)*2], bfr[nj >> 1][(nj & 1)*2 + 1]);
        }
    }

    #pragma unroll
    for (int mi = 0; mi < 3; mi++) {
        int rA = mi*16 + rA0, rB = rA + 8;
        #pragma unroll
        for (int nj = 0; nj < 4; nj++) {
            int c = nj*8 + colb;
            if (rA < WWIN) {
                bf162 p = bf162{__float2bfloat16(o[mi][nj][0]), __float2bfloat16(o[mi][nj][1])};
                *(bf162*)(out + ((size_t)w*WWIN + rA)*CDIM + h*HDIM + c) = p;
            }
            if (rB < WWIN) {
                bf162 p = bf162{__float2bfloat16(o[mi][nj][2]), __float2bfloat16(o[mi][nj][3])};
                *(bf162*)(out + ((size_t)w*WWIN + rB)*CDIM + h*HDIM + c) = p;
            }
        }
    }
}

// ---------------- host-side launch --------------------------
extern "C" void kernel_launch(void* const* d_in, const int* in_sizes, int n_in,
                              void* d_out, int out_size)
{
    const float* x     = (const float*)d_in[0];
    const float* n1g   = (const float*)d_in[1];
    const float* n1b   = (const float*)d_in[2];
    const float* qkv_w = (const float*)d_in[3];
    const float* qkv_b = (const float*)d_in[4];
    const float* bt    = (const float*)d_in[5];
    const float* pw    = (const float*)d_in[6];
    const float* pb    = (const float*)d_in[7];
    const float* n2g   = (const float*)d_in[8];
    const float* n2b   = (const float*)d_in[9];
    const float* f1w   = (const float*)d_in[10];
    const float* f1b   = (const float*)d_in[11];
    const float* f2w   = (const float*)d_in[12];
    const float* f2b   = (const float*)d_in[13];
    float* out = (float*)d_out;

    bf16 *h0b, *qkvb, *attb, *prjb, *mb, *f1buf, *wb;
    cudaGetSymbolAddress((void**)&h0b,  gb_h0);
    cudaGetSymbolAddress((void**)&qkvb, gb_qkv);
    cudaGetSymbolAddress((void**)&attb, gb_att);
    cudaGetSymbolAddress((void**)&prjb, gb_prj);
    cudaGetSymbolAddress((void**)&mb,   gb_m);
    cudaGetSymbolAddress((void**)&f1buf,gb_f1);
    cudaGetSymbolAddress((void**)&wb,   gb_w);

    cudaFuncSetAttribute(attn_mma_kernel,
                         cudaFuncAttributeMaxDynamicSharedMemorySize, ATT_SMEM);
    cudaFuncSetAttribute(bgemm_kernel<0,1>,
                         cudaFuncAttributeMaxDynamicSharedMemorySize, GM_SMEM);
    cudaFuncSetAttribute(bgemm_kernel<1,1>,
                         cudaFuncAttributeMaxDynamicSharedMemorySize, GM_SMEM);
    cudaFuncSetAttribute(bgemm_kernel<3,0>,
                         cudaFuncAttributeMaxDynamicSharedMemorySize, GM_SMEM);

    cvt_all_kernel<<<768, 256>>>((const float4*)qkv_w, (const float4*)pw,
                                 (const float4*)f1w,   (const float4*)f2w, wb);

    const int MBLK = NTOK / 128;   // 1344

    ln_roll_kernel<<<NTOK/16, 256>>>(x, n1g, n1b, h0b);
    bgemm_kernel<0,1><<<dim3(6, MBLK), 256, GM_SMEM>>>(h0b, wb + WOFF_QKV, qkv_b, nullptr, nullptr, qkvb, NTOK, 768, 256);
    attn_mma_kernel<<<NBWIN, 256, ATT_SMEM>>>(qkvb, bt, attb);
    bgemm_kernel<0,1><<<dim3(2, MBLK), 256, GM_SMEM>>>(attb, wb + WOFF_P, pb, nullptr, nullptr, prjb, NTOK, 256, 256);
    resid_ln2_kernel<<<NTOK/16, 256>>>(x, prjb, n2g, n2b, mb);
    bgemm_kernel<1,1><<<dim3(8, MBLK), 256, GM_SMEM>>>(mb, wb + WOFF_F1, f1b, nullptr, nullptr, f1buf, NTOK, 1024, 256);
    // FC2: out = x + rolled(prj) + f1 @ W2 + b2   (x1 recomputed in epilogue)
    bgemm_kernel<3,0><<<dim3(2, MBLK), 256, GM_SMEM>>>(f1buf, wb + WOFF_F2, f2b, x, prjb, out, NTOK, 256, 1024);
}